// round 3
// baseline (speedup 1.0000x reference)
#include <cuda_runtime.h>
#include <math.h>

// Problem constants (B=2, C=48, 32^3 volume)
#define BB   2
#define CC   48
#define SS   (32*32*32)          // 32768
#define OFFC 81

// ---------------- scratch (device globals; allocation-free) ----------------
__device__ float g_xn  [BB*CC*SS];   // 0: LayerNorm out (= attention shortcut)
__device__ float g_u   [BB*CC*SS];   // 1: p1 + gelu out (= gating "u")
__device__ float g_a1  [BB*CC*SS];   // 2: c0 out; later reused as gate product
__device__ float g_a2  [BB*CC*SS];   // 3: cs out (deform input)
__device__ float g_off [BB*OFFC*SS]; // 4: offset conv out
__device__ float g_a3  [BB*CC*SS];   // 5: deform out
__device__ float g_skip[BB*CC*SS];   // 6: feat/skip
__device__ float g_h1  [BB*CC*SS];   // 7: u1+bn1+lrelu out
__device__ float g_attn[BB*CC*SS];   // 8: attn
__device__ float g_dcwt[27*CC*CC];   // dc_w transposed to [tap][c][o]

// Device-side buffer selection: keeps kernel_launch free of ALL host API calls.
__device__ __forceinline__ float* bufsel(int id, const float* ext) {
    switch (id) {
        case 0: return g_xn;   case 1: return g_u;    case 2: return g_a1;
        case 3: return g_a2;   case 4: return g_off;  case 5: return g_a3;
        case 6: return g_skip; case 7: return g_h1;   case 8: return g_attn;
    }
    return (float*)ext;
}

// ---------------- LayerNorm over C per voxel ----------------
__global__ void k_ln(const float* __restrict__ x,
                     const float* __restrict__ ls,
                     const float* __restrict__ lb) {
    int i = blockIdx.x * blockDim.x + threadIdx.x;    // over BB*SS
    if (i >= BB * SS) return;
    int b = i >> 15, s = i & (SS - 1);
    const float* xb = x + (size_t)b * CC * SS + s;
    float v[CC];
    float mu = 0.f;
    #pragma unroll
    for (int c = 0; c < CC; c++) { v[c] = xb[c * SS]; mu += v[c]; }
    mu *= (1.f / CC);
    float var = 0.f;
    #pragma unroll
    for (int c = 0; c < CC; c++) { float d = v[c] - mu; var += d * d; }
    var *= (1.f / CC);
    float inv = rsqrtf(var + 1e-5f);
    float* ob = g_xn + (size_t)b * CC * SS + s;
    #pragma unroll
    for (int c = 0; c < CC; c++)
        ob[c * SS] = (v[c] - mu) * inv * ls[c] + lb[c];
}

// ---------------- 1x1x1 pointwise 48x48, output-stationary ----------------
// One thread = one voxel, all 48 output channels in registers.
// mode 0: out = gelu(acc + bias[o])
// mode 1: out = aux1 * (acc + bias[o])                     (gate = u * c1(a3))
// mode 2: out = aux1 + gamma[o]*(acc + bias[o] + aux2)     (skip = x + g*(p2+shortcut))
// mode 3: out = aux1 + acc + bias[o]                       (final = skip + pr(attn))
__global__ void __launch_bounds__(256) k_pw48(
    int in_id, const float* __restrict__ ext_in,
    const float* __restrict__ w, const float* __restrict__ bias,
    int a1_id, const float* __restrict__ ext_a1,
    int a2_id,
    const float* __restrict__ gamma,
    int out_id, float* __restrict__ ext_out,
    int mode)
{
    __shared__ float4 ws[CC * (CC / 4)];   // w[o][c] viewed as float4 over c
    __shared__ float  bs[CC];
    const float4* wg = (const float4*)w;
    for (int i = threadIdx.x; i < CC * CC / 4; i += blockDim.x) ws[i] = wg[i];
    if (threadIdx.x < CC) bs[threadIdx.x] = bias[threadIdx.x];
    __syncthreads();

    int i = blockIdx.x * blockDim.x + threadIdx.x;    // over BB*SS
    int b = i >> 15, s = i & (SS - 1);
    const float* in = bufsel(in_id, ext_in) + (size_t)b * CC * SS + s;

    float acc[CC];
    #pragma unroll
    for (int o = 0; o < CC; o++) acc[o] = 0.f;

    #pragma unroll 3
    for (int c4 = 0; c4 < CC / 4; c4++) {
        float v0 = in[(c4 * 4 + 0) * SS];
        float v1 = in[(c4 * 4 + 1) * SS];
        float v2 = in[(c4 * 4 + 2) * SS];
        float v3 = in[(c4 * 4 + 3) * SS];
        #pragma unroll
        for (int o = 0; o < CC; o++) {
            float4 wv = ws[o * (CC / 4) + c4];
            acc[o] += wv.x * v0 + wv.y * v1 + wv.z * v2 + wv.w * v3;
        }
    }

    size_t base = (size_t)b * CC * SS + s;
    float* outp = bufsel(out_id, (const float*)ext_out) + base;
    const float* a1p = bufsel(a1_id, ext_a1) + base;
    const float* a2p = g_xn + base;   // only used in mode 2

    if (mode == 0) {
        #pragma unroll
        for (int o = 0; o < CC; o++) {
            float v = acc[o] + bs[o];
            outp[o * SS] = 0.5f * v * (1.f + erff(v * 0.70710678118654752f));
        }
    } else if (mode == 1) {
        #pragma unroll
        for (int o = 0; o < CC; o++)
            outp[o * SS] = a1p[o * SS] * (acc[o] + bs[o]);
    } else if (mode == 2) {
        #pragma unroll
        for (int o = 0; o < CC; o++)
            outp[o * SS] = a1p[o * SS] + gamma[o] * (acc[o] + bs[o] + a2p[o * SS]);
    } else {
        #pragma unroll
        for (int o = 0; o < CC; o++)
            outp[o * SS] = a1p[o * SS] + acc[o] + bs[o];
    }
}

// ---------------- depthwise KxKxK (zero pad, dilation), templated ----------------
template<int K, int PAD, int DIL>
__global__ void k_dw(int in_id, const float* __restrict__ w,
                     const float* __restrict__ bias, int out_id) {
    __shared__ float ws[K * K * K];
    int c = blockIdx.y, b = blockIdx.z;
    for (int i = threadIdx.x; i < K * K * K; i += blockDim.x)
        ws[i] = w[c * K * K * K + i];
    __syncthreads();
    int s = blockIdx.x * blockDim.x + threadIdx.x;
    int z = s >> 10, y = (s >> 5) & 31, x = s & 31;
    const float* ib = bufsel(in_id, nullptr) + ((size_t)b * CC + c) * SS;
    float acc = bias[c];
    #pragma unroll
    for (int i = 0; i < K; i++) {
        int zz = z + i * DIL - PAD; if ((unsigned)zz >= 32u) continue;
        #pragma unroll
        for (int j = 0; j < K; j++) {
            int yy = y + j * DIL - PAD; if ((unsigned)yy >= 32u) continue;
            #pragma unroll
            for (int l = 0; l < K; l++) {
                int xx = x + l * DIL - PAD; if ((unsigned)xx >= 32u) continue;
                acc += ws[(i * K + j) * K + l] * ib[(zz << 10) + (yy << 5) + xx];
            }
        }
    }
    bufsel(out_id, nullptr)[((size_t)b * CC + c) * SS + s] = acc;
}

// ---------------- dense 3x3x3 conv (C=48 in), fused epilogues ----------------
// mode 0: out = acc + bias[o]                          (offset conv, O=81)
// mode 1: out = leaky(bn(acc))                         (u1)
// mode 2: out = leaky(bn(acc) + skip)                  (u2 -> attn)
__global__ void k_c3(int in_id, const float* __restrict__ w,
                     const float* __restrict__ bias,
                     const float* __restrict__ bs2, const float* __restrict__ bbp,
                     const float* __restrict__ bm, const float* __restrict__ bv,
                     int skip_id,
                     int out_id, int O, int mode) {
    __shared__ float ws[CC * 27];
    int o = blockIdx.y, b = blockIdx.z;
    for (int i = threadIdx.x; i < CC * 27; i += blockDim.x)
        ws[i] = w[o * CC * 27 + i];
    __syncthreads();
    int s = blockIdx.x * blockDim.x + threadIdx.x;
    int z = s >> 10, y = (s >> 5) & 31, x = s & 31;
    const float* ib = bufsel(in_id, nullptr) + (size_t)b * CC * SS;
    float acc = 0.f;
    for (int c = 0; c < CC; c++) {
        const float* ic = ib + c * SS;
        const float* wc = ws + c * 27;
        #pragma unroll
        for (int kd = 0; kd < 3; kd++) {
            int zz = z + kd - 1; if ((unsigned)zz >= 32u) continue;
            #pragma unroll
            for (int kh = 0; kh < 3; kh++) {
                int yy = y + kh - 1; if ((unsigned)yy >= 32u) continue;
                #pragma unroll
                for (int kw = 0; kw < 3; kw++) {
                    int xx = x + kw - 1; if ((unsigned)xx >= 32u) continue;
                    acc += wc[(kd * 3 + kh) * 3 + kw] * ic[(zz << 10) + (yy << 5) + xx];
                }
            }
        }
    }
    size_t oi = ((size_t)b * O + o) * SS + s;
    if (mode == 0) {
        bufsel(out_id, nullptr)[oi] = acc + bias[o];
    } else {
        float scale = bs2[o] * rsqrtf(bv[o] + 1e-5f);
        float h = acc * scale + (bbp[o] - bm[o] * scale);
        if (mode == 2) h += bufsel(skip_id, nullptr)[oi];
        bufsel(out_id, nullptr)[oi] = (h >= 0.f) ? h : 0.01f * h;
    }
}

// ---------------- transpose dc_w [o][c][k] -> [k][c][o] ----------------
__global__ void k_wt(const float* __restrict__ w) {
    int i = blockIdx.x * blockDim.x + threadIdx.x;
    if (i >= CC * CC * 27) return;
    int o = i / (CC * 27);
    int r = i - o * (CC * 27);
    int c = r / 27;
    int k = r - c * 27;
    g_dcwt[(k * CC + c) * CC + o] = w[i];
}

// ---------------- deformable conv 3x3x3: trilinear gather + per-tap 48x48 GEMM ----------------
__global__ void __launch_bounds__(128) k_deform(const float* __restrict__ dcb) {
    int s = blockIdx.x * blockDim.x + threadIdx.x;
    int b = blockIdx.y;
    int z = s >> 10, y = (s >> 5) & 31, x = s & 31;
    const float* a   = g_a2  + (size_t)b * CC * SS;
    const float* off = g_off + (size_t)b * OFFC * SS + s;
    float acc[CC];
    #pragma unroll
    for (int o = 0; o < CC; o++) acc[o] = 0.f;

    int k = 0;
    for (int kd = -1; kd <= 1; kd++)
    for (int kh = -1; kh <= 1; kh++)
    for (int kw = -1; kw <= 1; kw++) {
        float zf = (float)(z + kd) + off[(k * 3 + 0) * SS];
        float yf = (float)(y + kh) + off[(k * 3 + 1) * SS];
        float xf = (float)(x + kw) + off[(k * 3 + 2) * SS];
        float z0 = floorf(zf), y0 = floorf(yf), x0 = floorf(xf);
        float tz = zf - z0, ty = yf - y0, tx = xf - x0;
        int iz0 = (int)z0, iy0 = (int)y0, ix0 = (int)x0;

        int   idx8[8];
        float w8[8];
        #pragma unroll
        for (int dz = 0; dz < 2; dz++)
        #pragma unroll
        for (int dy = 0; dy < 2; dy++)
        #pragma unroll
        for (int dx = 0; dx < 2; dx++) {
            int j = dz * 4 + dy * 2 + dx;
            int zi = iz0 + dz, yi = iy0 + dy, xi = ix0 + dx;
            bool valid = (zi >= 0 && zi < 32 && yi >= 0 && yi < 32 && xi >= 0 && xi < 32);
            float wg = (dz ? tz : 1.f - tz) * (dy ? ty : 1.f - ty) * (dx ? tx : 1.f - tx);
            int zc = min(max(zi, 0), 31), yc = min(max(yi, 0), 31), xc = min(max(xi, 0), 31);
            idx8[j] = (zc << 10) + (yc << 5) + xc;
            w8[j] = valid ? wg : 0.f;
        }

        for (int c = 0; c < CC; c++) {
            const float* ac = a + c * SS;
            float val = w8[0] * ac[idx8[0]] + w8[1] * ac[idx8[1]]
                      + w8[2] * ac[idx8[2]] + w8[3] * ac[idx8[3]]
                      + w8[4] * ac[idx8[4]] + w8[5] * ac[idx8[5]]
                      + w8[6] * ac[idx8[6]] + w8[7] * ac[idx8[7]];
            const float* wt = g_dcwt + (k * CC + c) * CC;  // contiguous over o
            #pragma unroll
            for (int o = 0; o < CC; o++) acc[o] += wt[o] * val;
        }
        k++;
    }
    float* ob = g_a3 + (size_t)b * CC * SS + s;
    #pragma unroll
    for (int o = 0; o < CC; o++) ob[o * SS] = acc[o] + dcb[o];
}

// ---------------- launch: kernel launches ONLY, no other API calls ----------------
extern "C" void kernel_launch(void* const* d_in, const int* in_sizes, int n_in,
                              void* d_out, int out_size) {
    const float* x     = (const float*)d_in[0];
    const float* ln_s  = (const float*)d_in[1];
    const float* ln_b  = (const float*)d_in[2];
    const float* gamma = (const float*)d_in[3];
    const float* p1_w  = (const float*)d_in[4];
    const float* p1_b  = (const float*)d_in[5];
    const float* p2_w  = (const float*)d_in[6];
    const float* p2_b  = (const float*)d_in[7];
    const float* c0_w  = (const float*)d_in[8];
    const float* c0_b  = (const float*)d_in[9];
    const float* cs_w  = (const float*)d_in[10];
    const float* cs_b  = (const float*)d_in[11];
    const float* off_w = (const float*)d_in[12];
    const float* off_b = (const float*)d_in[13];
    const float* dc_w  = (const float*)d_in[14];
    const float* dc_b  = (const float*)d_in[15];
    const float* c1_w  = (const float*)d_in[16];
    const float* c1_b  = (const float*)d_in[17];
    const float* u1_w  = (const float*)d_in[18];
    const float* bn1_s = (const float*)d_in[19];
    const float* bn1_b = (const float*)d_in[20];
    const float* bn1_m = (const float*)d_in[21];
    const float* bn1_v = (const float*)d_in[22];
    const float* u2_w  = (const float*)d_in[23];
    const float* bn2_s = (const float*)d_in[24];
    const float* bn2_b = (const float*)d_in[25];
    const float* bn2_m = (const float*)d_in[26];
    const float* bn2_v = (const float*)d_in[27];
    const float* pr_w  = (const float*)d_in[28];
    const float* pr_b  = (const float*)d_in[29];
    float* out = (float*)d_out;

    dim3 pwGrid((BB * SS) / 256);
    dim3 c3Grid48(SS / 256, CC, BB);
    dim3 c3Grid81(SS / 256, OFFC, BB);
    dim3 dwGrid(SS / 256, CC, BB);

    // 1. LayerNorm -> g_xn (0)
    k_ln<<<(BB * SS) / 256, 256>>>(x, ln_s, ln_b);
    // 2. proj_1 + GELU: g_xn -> g_u (1)
    k_pw48<<<pwGrid, 256>>>(0, nullptr, p1_w, p1_b, -1, nullptr, -1, nullptr,
                            1, nullptr, 0);
    // 3. depthwise 5x5x5 pad 2: g_u -> g_a1 (2)
    k_dw<5, 2, 1><<<dwGrid, 256>>>(1, c0_w, c0_b, 2);
    // 4. depthwise 7x7x7 dil 3 pad 9: g_a1 -> g_a2 (3)
    k_dw<7, 9, 3><<<dwGrid, 256>>>(2, cs_w, cs_b, 3);
    // 5. offset conv 3x3x3 -> 81 channels: g_a2 -> g_off (4)
    k_c3<<<c3Grid81, 256>>>(3, off_w, off_b, nullptr, nullptr, nullptr, nullptr,
                            -1, 4, OFFC, 0);
    // 6. transpose deform weights
    k_wt<<<(CC * CC * 27 + 255) / 256, 256>>>(dc_w);
    // 7. deformable conv: (g_a2, g_off) -> g_a3 (5)
    k_deform<<<dim3(SS / 128, BB), 128>>>(dc_b);
    // 8. c1 1x1x1 + gate multiply: g_a3, aux g_u -> g_a1 (2, reuse)
    k_pw48<<<pwGrid, 256>>>(5, nullptr, c1_w, c1_b, 1, nullptr, -1, nullptr,
                            2, nullptr, 1);
    // 9. proj_2 + shortcut + gamma residual: g_a1, aux x, aux2 g_xn -> g_skip (6)
    k_pw48<<<pwGrid, 256>>>(2, nullptr, p2_w, p2_b, -1, x, 0, gamma,
                            6, nullptr, 2);
    // 10. u1 conv3 + BN1 + leaky: g_skip -> g_h1 (7)
    k_c3<<<c3Grid48, 256>>>(6, u1_w, nullptr, bn1_s, bn1_b, bn1_m, bn1_v,
                            -1, 7, CC, 1);
    // 11. u2 conv3 + BN2 + skip + leaky: g_h1 -> g_attn (8)
    k_c3<<<c3Grid48, 256>>>(7, u2_w, nullptr, bn2_s, bn2_b, bn2_m, bn2_v,
                            6, 8, CC, 2);
    // 12. projconv 1x1x1 + skip -> out (external)
    k_pw48<<<pwGrid, 256>>>(8, nullptr, pr_w, pr_b, 6, nullptr, -1, nullptr,
                            -1, out, 3);
}

// round 4
// speedup vs baseline: 2.2472x; 2.2472x over previous
#include <cuda_runtime.h>
#include <math.h>

// Problem constants (B=2, C=48, 32^3 volume)
#define BB   2
#define CC   48
#define SS   (32*32*32)          // 32768
#define OFFC 81

// ---------------- scratch (device globals; allocation-free) ----------------
__device__ float g_xn  [BB*CC*SS];   // 0: LayerNorm out (= attention shortcut)
__device__ float g_u   [BB*CC*SS];   // 1: p1 + gelu out (= gating "u")
__device__ float g_a1  [BB*CC*SS];   // 2: c0 out; later reused as gate product
__device__ float g_a2  [BB*CC*SS];   // 3: cs out (deform input)
__device__ float g_off [BB*OFFC*SS]; // 4: offset conv out
__device__ float g_a3  [BB*CC*SS];   // 5: deform out
__device__ float g_skip[BB*CC*SS];   // 6: feat/skip
__device__ float g_h1  [BB*CC*SS];   // 7: u1+bn1+lrelu out
__device__ float g_attn[BB*CC*SS];   // 8: attn
__device__ float g_dcwt[27*CC*CC];   // dc_w transposed to [tap][c][o]

// Device-side buffer selection: keeps kernel_launch free of ALL host API calls.
__device__ __forceinline__ float* bufsel(int id, const float* ext) {
    switch (id) {
        case 0: return g_xn;   case 1: return g_u;    case 2: return g_a1;
        case 3: return g_a2;   case 4: return g_off;  case 5: return g_a3;
        case 6: return g_skip; case 7: return g_h1;   case 8: return g_attn;
    }
    return (float*)ext;
}

// ---------------- LayerNorm over C per voxel ----------------
__global__ void k_ln(const float* __restrict__ x,
                     const float* __restrict__ ls,
                     const float* __restrict__ lb) {
    int i = blockIdx.x * blockDim.x + threadIdx.x;    // over BB*SS
    if (i >= BB * SS) return;
    int b = i >> 15, s = i & (SS - 1);
    const float* xb = x + (size_t)b * CC * SS + s;
    float v[CC];
    float mu = 0.f;
    #pragma unroll
    for (int c = 0; c < CC; c++) { v[c] = xb[c * SS]; mu += v[c]; }
    mu *= (1.f / CC);
    float var = 0.f;
    #pragma unroll
    for (int c = 0; c < CC; c++) { float d = v[c] - mu; var += d * d; }
    var *= (1.f / CC);
    float inv = rsqrtf(var + 1e-5f);
    float* ob = g_xn + (size_t)b * CC * SS + s;
    #pragma unroll
    for (int c = 0; c < CC; c++)
        ob[c * SS] = (v[c] - mu) * inv * ls[c] + lb[c];
}

// ---------------- 1x1x1 pointwise 48x48, output-stationary ----------------
// mode 0: out = gelu(acc + bias[o])
// mode 1: out = aux1 * (acc + bias[o])                     (gate = u * c1(a3))
// mode 2: out = aux1 + gamma[o]*(acc + bias[o] + aux2)     (skip = x + g*(p2+shortcut))
// mode 3: out = aux1 + acc + bias[o]                       (final = skip + pr(attn))
__global__ void __launch_bounds__(256) k_pw48(
    int in_id, const float* __restrict__ ext_in,
    const float* __restrict__ w, const float* __restrict__ bias,
    int a1_id, const float* __restrict__ ext_a1,
    int a2_id,
    const float* __restrict__ gamma,
    int out_id, float* __restrict__ ext_out,
    int mode)
{
    __shared__ float4 ws[CC * (CC / 4)];   // w[o][c] viewed as float4 over c
    __shared__ float  bs[CC];
    const float4* wg = (const float4*)w;
    for (int i = threadIdx.x; i < CC * CC / 4; i += blockDim.x) ws[i] = wg[i];
    if (threadIdx.x < CC) bs[threadIdx.x] = bias[threadIdx.x];
    __syncthreads();

    int i = blockIdx.x * blockDim.x + threadIdx.x;    // over BB*SS
    int b = i >> 15, s = i & (SS - 1);
    const float* in = bufsel(in_id, ext_in) + (size_t)b * CC * SS + s;

    float acc[CC];
    #pragma unroll
    for (int o = 0; o < CC; o++) acc[o] = 0.f;

    #pragma unroll 3
    for (int c4 = 0; c4 < CC / 4; c4++) {
        float v0 = in[(c4 * 4 + 0) * SS];
        float v1 = in[(c4 * 4 + 1) * SS];
        float v2 = in[(c4 * 4 + 2) * SS];
        float v3 = in[(c4 * 4 + 3) * SS];
        #pragma unroll
        for (int o = 0; o < CC; o++) {
            float4 wv = ws[o * (CC / 4) + c4];
            acc[o] += wv.x * v0 + wv.y * v1 + wv.z * v2 + wv.w * v3;
        }
    }

    size_t base = (size_t)b * CC * SS + s;
    float* outp = bufsel(out_id, (const float*)ext_out) + base;
    const float* a1p = bufsel(a1_id, ext_a1) + base;
    const float* a2p = g_xn + base;   // only used in mode 2

    if (mode == 0) {
        #pragma unroll
        for (int o = 0; o < CC; o++) {
            float v = acc[o] + bs[o];
            outp[o * SS] = 0.5f * v * (1.f + erff(v * 0.70710678118654752f));
        }
    } else if (mode == 1) {
        #pragma unroll
        for (int o = 0; o < CC; o++)
            outp[o * SS] = a1p[o * SS] * (acc[o] + bs[o]);
    } else if (mode == 2) {
        #pragma unroll
        for (int o = 0; o < CC; o++)
            outp[o * SS] = a1p[o * SS] + gamma[o] * (acc[o] + bs[o] + a2p[o * SS]);
    } else {
        #pragma unroll
        for (int o = 0; o < CC; o++)
            outp[o * SS] = a1p[o * SS] + acc[o] + bs[o];
    }
}

// ---------------- depthwise KxKxK (zero pad, dilation), templated ----------------
template<int K, int PAD, int DIL>
__global__ void k_dw(int in_id, const float* __restrict__ w,
                     const float* __restrict__ bias, int out_id) {
    __shared__ float ws[K * K * K];
    int c = blockIdx.y, b = blockIdx.z;
    for (int i = threadIdx.x; i < K * K * K; i += blockDim.x)
        ws[i] = w[c * K * K * K + i];
    __syncthreads();
    int s = blockIdx.x * blockDim.x + threadIdx.x;
    int z = s >> 10, y = (s >> 5) & 31, x = s & 31;
    const float* ib = bufsel(in_id, nullptr) + ((size_t)b * CC + c) * SS;
    float acc = bias[c];
    #pragma unroll
    for (int i = 0; i < K; i++) {
        int zz = z + i * DIL - PAD; if ((unsigned)zz >= 32u) continue;
        #pragma unroll
        for (int j = 0; j < K; j++) {
            int yy = y + j * DIL - PAD; if ((unsigned)yy >= 32u) continue;
            #pragma unroll
            for (int l = 0; l < K; l++) {
                int xx = x + l * DIL - PAD; if ((unsigned)xx >= 32u) continue;
                acc += ws[(i * K + j) * K + l] * ib[(zz << 10) + (yy << 5) + xx];
            }
        }
    }
    bufsel(out_id, nullptr)[((size_t)b * CC + c) * SS + s] = acc;
}

// ---------------- dense 3x3x3 conv, input-stationary, NO outputs/thread ----------------
// Each thread owns one voxel and NO output-channel accumulators. Weights for a
// CCH-channel slice are staged in smem as [cL][tap][o] (o contiguous, float4).
// Input voxel loaded once per (c,tap), reused across all NO outputs.
// mode 0: out = acc + bias[o]                          (offset conv chunks)
// mode 1: out = leaky(bn(acc))                         (u1)
// mode 2: out = leaky(bn(acc) + skip)                  (u2 -> attn)
template<int NO, int NO4, int CCH>
__global__ void __launch_bounds__(256) k_c3g(
    int in_id, const float* __restrict__ w,
    const float* __restrict__ bias,
    const float* __restrict__ bs2, const float* __restrict__ bbp,
    const float* __restrict__ bm, const float* __restrict__ bv,
    int skip_id, int out_id, int O, int mode)
{
    __shared__ float ws[CCH * 27 * NO4];
    const int o0 = blockIdx.y * NO;
    const int b  = blockIdx.z;
    const int s  = blockIdx.x * blockDim.x + threadIdx.x;
    const int z = s >> 10, y = (s >> 5) & 31, x = s & 31;
    const float* ib = bufsel(in_id, nullptr) + (size_t)b * CC * SS;

    float acc[NO];
    #pragma unroll
    for (int o = 0; o < NO; o++) acc[o] = 0.f;

    for (int cbase = 0; cbase < CC; cbase += CCH) {
        __syncthreads();
        // stage weights: global (o0+oL)*CC*27 + (cbase+cL)*27 + tap  -> ws[(cL*27+tap)*NO4 + oL]
        for (int gidx = threadIdx.x; gidx < NO * CCH * 27; gidx += blockDim.x) {
            int oL  = gidx / (CCH * 27);
            int r   = gidx - oL * (CCH * 27);
            int cL  = r / 27;
            int tap = r - cL * 27;
            ws[(cL * 27 + tap) * NO4 + oL] =
                w[(size_t)(o0 + oL) * (CC * 27) + (cbase + cL) * 27 + tap];
        }
        __syncthreads();

        for (int cL = 0; cL < CCH; cL++) {
            const float* ic = ib + (cbase + cL) * SS;
            // load the 27 neighborhood values once (predicated), then FMA fan-out
            float v[27];
            #pragma unroll
            for (int kd = 0; kd < 3; kd++) {
                int zz = z + kd - 1; bool vz = (unsigned)zz < 32u;
                #pragma unroll
                for (int kh = 0; kh < 3; kh++) {
                    int yy = y + kh - 1; bool vy = (unsigned)yy < 32u;
                    #pragma unroll
                    for (int kw = 0; kw < 3; kw++) {
                        int xx = x + kw - 1;
                        bool ok = vz && vy && ((unsigned)xx < 32u);
                        int tap = (kd * 3 + kh) * 3 + kw;
                        v[tap] = ok ? ic[(zz << 10) + (yy << 5) + xx] : 0.f;
                    }
                }
            }
            const float4* wrow = (const float4*)(ws + cL * 27 * NO4);
            #pragma unroll
            for (int tap = 0; tap < 27; tap++) {
                float vv = v[tap];
                #pragma unroll
                for (int o4 = 0; o4 < NO4 / 4; o4++) {
                    float4 wv = wrow[tap * (NO4 / 4) + o4];
                    if (o4 * 4 + 0 < NO) acc[o4 * 4 + 0] += wv.x * vv;
                    if (o4 * 4 + 1 < NO) acc[o4 * 4 + 1] += wv.y * vv;
                    if (o4 * 4 + 2 < NO) acc[o4 * 4 + 2] += wv.z * vv;
                    if (o4 * 4 + 3 < NO) acc[o4 * 4 + 3] += wv.w * vv;
                }
            }
        }
    }

    float* outb = bufsel(out_id, nullptr) + (size_t)b * O * SS + s;
    if (mode == 0) {
        #pragma unroll
        for (int o = 0; o < NO; o++)
            outb[(o0 + o) * SS] = acc[o] + bias[o0 + o];
    } else {
        const float* skp = (mode == 2) ? bufsel(skip_id, nullptr) + (size_t)b * O * SS + s
                                       : nullptr;
        #pragma unroll
        for (int o = 0; o < NO; o++) {
            int og = o0 + o;
            float scale = bs2[og] * rsqrtf(bv[og] + 1e-5f);
            float h = acc[o] * scale + (bbp[og] - bm[og] * scale);
            if (mode == 2) h += skp[og * SS];
            outb[og * SS] = (h >= 0.f) ? h : 0.01f * h;
        }
    }
}

// ---------------- transpose dc_w [o][c][k] -> [k][c][o] ----------------
__global__ void k_wt(const float* __restrict__ w) {
    int i = blockIdx.x * blockDim.x + threadIdx.x;
    if (i >= CC * CC * 27) return;
    int o = i / (CC * 27);
    int r = i - o * (CC * 27);
    int c = r / 27;
    int k = r - c * 27;
    g_dcwt[(k * CC + c) * CC + o] = w[i];
}

// ---------------- deformable conv 3x3x3: trilinear gather + per-tap 48x48 GEMM ----------------
__global__ void __launch_bounds__(128) k_deform(const float* __restrict__ dcb) {
    int s = blockIdx.x * blockDim.x + threadIdx.x;
    int b = blockIdx.y;
    int z = s >> 10, y = (s >> 5) & 31, x = s & 31;
    const float* a   = g_a2  + (size_t)b * CC * SS;
    const float* off = g_off + (size_t)b * OFFC * SS + s;
    float acc[CC];
    #pragma unroll
    for (int o = 0; o < CC; o++) acc[o] = 0.f;

    int k = 0;
    for (int kd = -1; kd <= 1; kd++)
    for (int kh = -1; kh <= 1; kh++)
    for (int kw = -1; kw <= 1; kw++) {
        float zf = (float)(z + kd) + off[(k * 3 + 0) * SS];
        float yf = (float)(y + kh) + off[(k * 3 + 1) * SS];
        float xf = (float)(x + kw) + off[(k * 3 + 2) * SS];
        float z0 = floorf(zf), y0 = floorf(yf), x0 = floorf(xf);
        float tz = zf - z0, ty = yf - y0, tx = xf - x0;
        int iz0 = (int)z0, iy0 = (int)y0, ix0 = (int)x0;

        int   idx8[8];
        float w8[8];
        #pragma unroll
        for (int dz = 0; dz < 2; dz++)
        #pragma unroll
        for (int dy = 0; dy < 2; dy++)
        #pragma unroll
        for (int dx = 0; dx < 2; dx++) {
            int j = dz * 4 + dy * 2 + dx;
            int zi = iz0 + dz, yi = iy0 + dy, xi = ix0 + dx;
            bool valid = (zi >= 0 && zi < 32 && yi >= 0 && yi < 32 && xi >= 0 && xi < 32);
            float wg = (dz ? tz : 1.f - tz) * (dy ? ty : 1.f - ty) * (dx ? tx : 1.f - tx);
            int zc = min(max(zi, 0), 31), yc = min(max(yi, 0), 31), xc = min(max(xi, 0), 31);
            idx8[j] = (zc << 10) + (yc << 5) + xc;
            w8[j] = valid ? wg : 0.f;
        }

        for (int c = 0; c < CC; c++) {
            const float* ac = a + c * SS;
            float val = w8[0] * ac[idx8[0]] + w8[1] * ac[idx8[1]]
                      + w8[2] * ac[idx8[2]] + w8[3] * ac[idx8[3]]
                      + w8[4] * ac[idx8[4]] + w8[5] * ac[idx8[5]]
                      + w8[6] * ac[idx8[6]] + w8[7] * ac[idx8[7]];
            const float* wt = g_dcwt + (k * CC + c) * CC;  // contiguous over o
            #pragma unroll
            for (int o = 0; o < CC; o++) acc[o] += wt[o] * val;
        }
        k++;
    }
    float* ob = g_a3 + (size_t)b * CC * SS + s;
    #pragma unroll
    for (int o = 0; o < CC; o++) ob[o * SS] = acc[o] + dcb[o];
}

// ---------------- launch: kernel launches ONLY, no other API calls ----------------
extern "C" void kernel_launch(void* const* d_in, const int* in_sizes, int n_in,
                              void* d_out, int out_size) {
    const float* x     = (const float*)d_in[0];
    const float* ln_s  = (const float*)d_in[1];
    const float* ln_b  = (const float*)d_in[2];
    const float* gamma = (const float*)d_in[3];
    const float* p1_w  = (const float*)d_in[4];
    const float* p1_b  = (const float*)d_in[5];
    const float* p2_w  = (const float*)d_in[6];
    const float* p2_b  = (const float*)d_in[7];
    const float* c0_w  = (const float*)d_in[8];
    const float* c0_b  = (const float*)d_in[9];
    const float* cs_w  = (const float*)d_in[10];
    const float* cs_b  = (const float*)d_in[11];
    const float* off_w = (const float*)d_in[12];
    const float* off_b = (const float*)d_in[13];
    const float* dc_w  = (const float*)d_in[14];
    const float* dc_b  = (const float*)d_in[15];
    const float* c1_w  = (const float*)d_in[16];
    const float* c1_b  = (const float*)d_in[17];
    const float* u1_w  = (const float*)d_in[18];
    const float* bn1_s = (const float*)d_in[19];
    const float* bn1_b = (const float*)d_in[20];
    const float* bn1_m = (const float*)d_in[21];
    const float* bn1_v = (const float*)d_in[22];
    const float* u2_w  = (const float*)d_in[23];
    const float* bn2_s = (const float*)d_in[24];
    const float* bn2_b = (const float*)d_in[25];
    const float* bn2_m = (const float*)d_in[26];
    const float* bn2_v = (const float*)d_in[27];
    const float* pr_w  = (const float*)d_in[28];
    const float* pr_b  = (const float*)d_in[29];
    float* out = (float*)d_out;

    dim3 pwGrid((BB * SS) / 256);
    dim3 dwGrid(SS / 256, CC, BB);
    dim3 c3OffGrid(SS / 256, 3, BB);   // 3 chunks of 27 output channels
    dim3 c3UGrid(SS / 256, 1, BB);     // 48 output channels in one chunk

    // 1. LayerNorm -> g_xn (0)
    k_ln<<<(BB * SS) / 256, 256>>>(x, ln_s, ln_b);
    // 2. proj_1 + GELU: g_xn -> g_u (1)
    k_pw48<<<pwGrid, 256>>>(0, nullptr, p1_w, p1_b, -1, nullptr, -1, nullptr,
                            1, nullptr, 0);
    // 3. depthwise 5x5x5 pad 2: g_u -> g_a1 (2)
    k_dw<5, 2, 1><<<dwGrid, 256>>>(1, c0_w, c0_b, 2);
    // 4. depthwise 7x7x7 dil 3 pad 9: g_a1 -> g_a2 (3)
    k_dw<7, 9, 3><<<dwGrid, 256>>>(2, cs_w, cs_b, 3);
    // 5. offset conv 3x3x3 -> 81 channels: g_a2 -> g_off (4)
    k_c3g<27, 28, 8><<<c3OffGrid, 256>>>(3, off_w, off_b,
                                         nullptr, nullptr, nullptr, nullptr,
                                         -1, 4, OFFC, 0);
    // 6. transpose deform weights
    k_wt<<<(CC * CC * 27 + 255) / 256, 256>>>(dc_w);
    // 7. deformable conv: (g_a2, g_off) -> g_a3 (5)
    k_deform<<<dim3(SS / 128, BB), 128>>>(dc_b);
    // 8. c1 1x1x1 + gate multiply: g_a3, aux g_u -> g_a1 (2, reuse)
    k_pw48<<<pwGrid, 256>>>(5, nullptr, c1_w, c1_b, 1, nullptr, -1, nullptr,
                            2, nullptr, 1);
    // 9. proj_2 + shortcut + gamma residual: g_a1, aux x, aux2 g_xn -> g_skip (6)
    k_pw48<<<pwGrid, 256>>>(2, nullptr, p2_w, p2_b, -1, x, 0, gamma,
                            6, nullptr, 2);
    // 10. u1 conv3 + BN1 + leaky: g_skip -> g_h1 (7)
    k_c3g<48, 48, 8><<<c3UGrid, 256>>>(6, u1_w, nullptr,
                                       bn1_s, bn1_b, bn1_m, bn1_v,
                                       -1, 7, CC, 1);
    // 11. u2 conv3 + BN2 + skip + leaky: g_h1 -> g_attn (8)
    k_c3g<48, 48, 8><<<c3UGrid, 256>>>(7, u2_w, nullptr,
                                       bn2_s, bn2_b, bn2_m, bn2_v,
                                       6, 8, CC, 2);
    // 12. projconv 1x1x1 + skip -> out (external)
    k_pw48<<<pwGrid, 256>>>(8, nullptr, pr_w, pr_b, 6, nullptr, -1, nullptr,
                            -1, out, 3);
}

// round 5
// speedup vs baseline: 2.5744x; 1.1456x over previous
#include <cuda_runtime.h>
#include <math.h>

// Problem constants (B=2, C=48, 32^3 volume)
#define BB   2
#define CC   48
#define SS   (32*32*32)          // 32768
#define OFFC 81

typedef unsigned long long ull;

// ---------------- f32x2 packed helpers (sm_100+) ----------------
__device__ __forceinline__ ull pack2(float a, float b) {
    ull r;
    asm("mov.b64 %0, {%1, %2};" : "=l"(r) : "f"(a), "f"(b));
    return r;
}
__device__ __forceinline__ void fma2(ull& d, ull a, ull b) {
    asm("fma.rn.f32x2 %0, %1, %2, %0;" : "+l"(d) : "l"(a), "l"(b));
}
__device__ __forceinline__ void unpack2(float& lo, float& hi, ull v) {
    asm("mov.b64 {%0, %1}, %2;" : "=f"(lo), "=f"(hi) : "l"(v));
}

// ---------------- scratch (device globals; allocation-free) ----------------
__device__ float g_xn  [BB*CC*SS];   // 0
__device__ float g_u   [BB*CC*SS];   // 1
__device__ float g_a1  [BB*CC*SS];   // 2
__device__ float g_a2  [BB*CC*SS];   // 3
__device__ float g_off [BB*OFFC*SS]; // 4
__device__ float g_a3  [BB*CC*SS];   // 5
__device__ float g_skip[BB*CC*SS];   // 6
__device__ float g_h1  [BB*CC*SS];   // 7
__device__ float g_attn[BB*CC*SS];   // 8
__device__ float g_dcwt[27*CC*CC];   // dc_w transposed to [tap][c][o]

__device__ __forceinline__ float* bufsel(int id, const float* ext) {
    switch (id) {
        case 0: return g_xn;   case 1: return g_u;    case 2: return g_a1;
        case 3: return g_a2;   case 4: return g_off;  case 5: return g_a3;
        case 6: return g_skip; case 7: return g_h1;   case 8: return g_attn;
    }
    return (float*)ext;
}

// ---------------- LayerNorm over C per voxel ----------------
__global__ void k_ln(const float* __restrict__ x,
                     const float* __restrict__ ls,
                     const float* __restrict__ lb) {
    int i = blockIdx.x * blockDim.x + threadIdx.x;
    if (i >= BB * SS) return;
    int b = i >> 15, s = i & (SS - 1);
    const float* xb = x + (size_t)b * CC * SS + s;
    float v[CC];
    float mu = 0.f;
    #pragma unroll
    for (int c = 0; c < CC; c++) { v[c] = xb[c * SS]; mu += v[c]; }
    mu *= (1.f / CC);
    float var = 0.f;
    #pragma unroll
    for (int c = 0; c < CC; c++) { float d = v[c] - mu; var += d * d; }
    var *= (1.f / CC);
    float inv = rsqrtf(var + 1e-5f);
    float* ob = g_xn + (size_t)b * CC * SS + s;
    #pragma unroll
    for (int c = 0; c < CC; c++)
        ob[c * SS] = (v[c] - mu) * inv * ls[c] + lb[c];
}

// ---------------- 1x1x1 pointwise 48x48, f32x2 output pairs ----------------
// mode 0: gelu; 1: gate mult; 2: skip+gamma residual; 3: skip add
__global__ void __launch_bounds__(256) k_pw48(
    int in_id, const float* __restrict__ ext_in,
    const float* __restrict__ w, const float* __restrict__ bias,
    int a1_id, const float* __restrict__ ext_a1,
    int a2_id,
    const float* __restrict__ gamma,
    int out_id, float* __restrict__ ext_out,
    int mode)
{
    __shared__ __align__(16) float ws2[CC * CC];   // [c][o], o contiguous
    __shared__ float bs[CC];
    for (int i = threadIdx.x; i < CC * CC; i += blockDim.x) {
        int o = i / CC, c = i - o * CC;
        ws2[c * CC + o] = w[i];
    }
    if (threadIdx.x < CC) bs[threadIdx.x] = bias[threadIdx.x];
    __syncthreads();

    int i = blockIdx.x * blockDim.x + threadIdx.x;
    int b = i >> 15, s = i & (SS - 1);
    const float* in = bufsel(in_id, ext_in) + (size_t)b * CC * SS + s;

    ull acc2[CC / 2];
    #pragma unroll
    for (int q = 0; q < CC / 2; q++) acc2[q] = 0ull;

    const ulonglong2* wrow = (const ulonglong2*)ws2;
    #pragma unroll 4
    for (int c = 0; c < CC; c++) {
        float v = in[c * SS];
        ull vv = pack2(v, v);
        #pragma unroll
        for (int q = 0; q < CC / 4; q++) {
            ulonglong2 wq = wrow[c * (CC / 4) + q];
            fma2(acc2[2 * q + 0], wq.x, vv);
            fma2(acc2[2 * q + 1], wq.y, vv);
        }
    }

    float acc[CC];
    #pragma unroll
    for (int q = 0; q < CC / 2; q++) unpack2(acc[2 * q], acc[2 * q + 1], acc2[q]);

    size_t base = (size_t)b * CC * SS + s;
    float* outp = bufsel(out_id, (const float*)ext_out) + base;
    const float* a1p = bufsel(a1_id, ext_a1) + base;
    const float* a2p = g_xn + base;

    if (mode == 0) {
        #pragma unroll
        for (int o = 0; o < CC; o++) {
            float v = acc[o] + bs[o];
            outp[o * SS] = 0.5f * v * (1.f + erff(v * 0.70710678118654752f));
        }
    } else if (mode == 1) {
        #pragma unroll
        for (int o = 0; o < CC; o++)
            outp[o * SS] = a1p[o * SS] * (acc[o] + bs[o]);
    } else if (mode == 2) {
        #pragma unroll
        for (int o = 0; o < CC; o++)
            outp[o * SS] = a1p[o * SS] + gamma[o] * (acc[o] + bs[o] + a2p[o * SS]);
    } else {
        #pragma unroll
        for (int o = 0; o < CC; o++)
            outp[o * SS] = a1p[o * SS] + acc[o] + bs[o];
    }
}

// ---------------- depthwise KxKxK, dynamic valid tap ranges ----------------
template<int K, int PAD, int DIL>
__global__ void k_dw(int in_id, const float* __restrict__ w,
                     const float* __restrict__ bias, int out_id) {
    __shared__ float ws[K * K * K];
    int c = blockIdx.y, b = blockIdx.z;
    for (int i = threadIdx.x; i < K * K * K; i += blockDim.x)
        ws[i] = w[c * K * K * K + i];
    __syncthreads();
    int s = blockIdx.x * blockDim.x + threadIdx.x;
    int z = s >> 10, y = (s >> 5) & 31, x = s & 31;
    const float* ib = bufsel(in_id, nullptr) + ((size_t)b * CC + c) * SS;

    // valid tap range per dim: 0 <= coord + t*DIL - PAD < 32
    auto lo = [](int coord) { int t = PAD - coord; return (t > 0) ? (t + DIL - 1) / DIL : 0; };
    auto hi = [](int coord) { int t = 31 + PAD - coord; int h = t / DIL; return (h < K - 1) ? h : K - 1; };
    int ilo = lo(z), ihi = hi(z);
    int jlo = lo(y), jhi = hi(y);
    int llo = lo(x), lhi = hi(x);

    float acc = bias[c];
    for (int i = ilo; i <= ihi; i++) {
        int zz = z + i * DIL - PAD;
        for (int j = jlo; j <= jhi; j++) {
            int yy = y + j * DIL - PAD;
            const float* row = ib + (zz << 10) + (yy << 5) + (x - PAD);
            const float* wr  = ws + (i * K + j) * K;
            for (int l = llo; l <= lhi; l++)
                acc += wr[l] * row[l * DIL];
        }
    }
    bufsel(out_id, nullptr)[((size_t)b * CC + c) * SS + s] = acc;
}

// ---------------- dense 3x3x3 conv, input-stationary, f32x2 output pairs ----------------
// Weights staged as [cL][tap][o] (NO4 floats, 16B-aligned rows).
// mode 0: +bias; 1: leaky(bn); 2: leaky(bn + skip)
template<int NO, int NO4, int CCH>
__global__ void __launch_bounds__(256) k_c3g(
    int in_id, const float* __restrict__ w,
    const float* __restrict__ bias,
    const float* __restrict__ bs2, const float* __restrict__ bbp,
    const float* __restrict__ bm, const float* __restrict__ bv,
    int skip_id, int out_id, int O, int mode)
{
    __shared__ __align__(16) float ws[CCH * 27 * NO4];
    const int o0 = blockIdx.y * NO;
    const int b  = blockIdx.z;
    const int s  = blockIdx.x * blockDim.x + threadIdx.x;
    const int z = s >> 10, y = (s >> 5) & 31, x = s & 31;
    const float* ib = bufsel(in_id, nullptr) + (size_t)b * CC * SS;

    ull acc2[NO4 / 2];
    #pragma unroll
    for (int q = 0; q < NO4 / 2; q++) acc2[q] = 0ull;

    for (int cbase = 0; cbase < CC; cbase += CCH) {
        __syncthreads();
        for (int gidx = threadIdx.x; gidx < NO * CCH * 27; gidx += blockDim.x) {
            int oL  = gidx / (CCH * 27);
            int r   = gidx - oL * (CCH * 27);
            int cL  = r / 27;
            int tap = r - cL * 27;
            ws[(cL * 27 + tap) * NO4 + oL] =
                w[(size_t)(o0 + oL) * (CC * 27) + (cbase + cL) * 27 + tap];
        }
        __syncthreads();

        for (int cL = 0; cL < CCH; cL++) {
            const float* ic = ib + (cbase + cL) * SS;
            float v[27];
            #pragma unroll
            for (int kd = 0; kd < 3; kd++) {
                int zz = z + kd - 1; bool vz = (unsigned)zz < 32u;
                #pragma unroll
                for (int kh = 0; kh < 3; kh++) {
                    int yy = y + kh - 1; bool vy = (unsigned)yy < 32u;
                    #pragma unroll
                    for (int kw = 0; kw < 3; kw++) {
                        int xx = x + kw - 1;
                        bool ok = vz && vy && ((unsigned)xx < 32u);
                        v[(kd * 3 + kh) * 3 + kw] = ok ? ic[(zz << 10) + (yy << 5) + xx] : 0.f;
                    }
                }
            }
            const ulonglong2* wrow = (const ulonglong2*)(ws + cL * 27 * NO4);
            #pragma unroll
            for (int tap = 0; tap < 27; tap++) {
                ull vv = pack2(v[tap], v[tap]);
                #pragma unroll
                for (int q = 0; q < NO4 / 4; q++) {
                    ulonglong2 wq = wrow[tap * (NO4 / 4) + q];
                    fma2(acc2[2 * q + 0], wq.x, vv);
                    fma2(acc2[2 * q + 1], wq.y, vv);
                }
            }
        }
    }

    float acc[NO4];
    #pragma unroll
    for (int q = 0; q < NO4 / 2; q++) unpack2(acc[2 * q], acc[2 * q + 1], acc2[q]);

    float* outb = bufsel(out_id, nullptr) + (size_t)b * O * SS + s;
    if (mode == 0) {
        #pragma unroll
        for (int o = 0; o < NO; o++)
            outb[(o0 + o) * SS] = acc[o] + bias[o0 + o];
    } else {
        const float* skp = (mode == 2) ? bufsel(skip_id, nullptr) + (size_t)b * O * SS + s
                                       : nullptr;
        #pragma unroll
        for (int o = 0; o < NO; o++) {
            int og = o0 + o;
            float scale = bs2[og] * rsqrtf(bv[og] + 1e-5f);
            float h = acc[o] * scale + (bbp[og] - bm[og] * scale);
            if (mode == 2) h += skp[og * SS];
            outb[og * SS] = (h >= 0.f) ? h : 0.01f * h;
        }
    }
}

// ---------------- transpose dc_w [o][c][k] -> [k][c][o] ----------------
__global__ void k_wt(const float* __restrict__ w) {
    int i = blockIdx.x * blockDim.x + threadIdx.x;
    if (i >= CC * CC * 27) return;
    int o = i / (CC * 27);
    int r = i - o * (CC * 27);
    int c = r / 27;
    int k = r - c * 27;
    g_dcwt[(k * CC + c) * CC + o] = w[i];
}

// ---------------- deformable conv: smem weight staging + f32x2 ----------------
__global__ void __launch_bounds__(256) k_deform(const float* __restrict__ dcb) {
    __shared__ __align__(16) float wt_s[CC * CC];   // [c][o] for current tap
    int s = blockIdx.x * blockDim.x + threadIdx.x;
    int b = blockIdx.y;
    int z = s >> 10, y = (s >> 5) & 31, x = s & 31;
    const float* a   = g_a2  + (size_t)b * CC * SS;
    const float* off = g_off + (size_t)b * OFFC * SS + s;

    ull acc2[CC / 2];
    #pragma unroll
    for (int q = 0; q < CC / 2; q++) acc2[q] = 0ull;

    int k = 0;
    #pragma unroll 1
    for (int kd = -1; kd <= 1; kd++)
    for (int kh = -1; kh <= 1; kh++)
    for (int kw = -1; kw <= 1; kw++) {
        // stage this tap's 48x48 weight tile
        __syncthreads();
        {
            const float4* src = (const float4*)(g_dcwt + k * CC * CC);
            float4* dst = (float4*)wt_s;
            for (int i = threadIdx.x; i < CC * CC / 4; i += blockDim.x)
                dst[i] = src[i];
        }
        __syncthreads();

        float zf = (float)(z + kd) + off[(k * 3 + 0) * SS];
        float yf = (float)(y + kh) + off[(k * 3 + 1) * SS];
        float xf = (float)(x + kw) + off[(k * 3 + 2) * SS];
        float z0 = floorf(zf), y0 = floorf(yf), x0 = floorf(xf);
        float tz = zf - z0, ty = yf - y0, tx = xf - x0;
        int iz0 = (int)z0, iy0 = (int)y0, ix0 = (int)x0;

        int idx8[8];
        ull w8v[8];
        #pragma unroll
        for (int dz = 0; dz < 2; dz++)
        #pragma unroll
        for (int dy = 0; dy < 2; dy++)
        #pragma unroll
        for (int dx = 0; dx < 2; dx++) {
            int j = dz * 4 + dy * 2 + dx;
            int zi = iz0 + dz, yi = iy0 + dy, xi = ix0 + dx;
            bool valid = (zi >= 0 && zi < 32 && yi >= 0 && yi < 32 && xi >= 0 && xi < 32);
            float wg = (dz ? tz : 1.f - tz) * (dy ? ty : 1.f - ty) * (dx ? tx : 1.f - tx);
            int zc = min(max(zi, 0), 31), yc = min(max(yi, 0), 31), xc = min(max(xi, 0), 31);
            idx8[j] = (zc << 10) + (yc << 5) + xc;
            float wf = valid ? wg : 0.f;
            w8v[j] = pack2(wf, wf);
        }

        for (int c = 0; c < CC; c += 2) {
            const float* ac0 = a + c * SS;
            const float* ac1 = ac0 + SS;
            ull valv = 0ull;
            #pragma unroll
            for (int j = 0; j < 8; j++)
                fma2(valv, pack2(ac0[idx8[j]], ac1[idx8[j]]), w8v[j]);
            float v0, v1;
            unpack2(v0, v1, valv);
            ull vv0 = pack2(v0, v0), vv1 = pack2(v1, v1);

            const ulonglong2* w0 = (const ulonglong2*)(wt_s + (c + 0) * CC);
            const ulonglong2* w1 = (const ulonglong2*)(wt_s + (c + 1) * CC);
            #pragma unroll
            for (int q = 0; q < CC / 4; q++) {
                ulonglong2 wa = w0[q];
                fma2(acc2[2 * q + 0], wa.x, vv0);
                fma2(acc2[2 * q + 1], wa.y, vv0);
            }
            #pragma unroll
            for (int q = 0; q < CC / 4; q++) {
                ulonglong2 wb = w1[q];
                fma2(acc2[2 * q + 0], wb.x, vv1);
                fma2(acc2[2 * q + 1], wb.y, vv1);
            }
        }
        k++;
    }

    float* ob = g_a3 + (size_t)b * CC * SS + s;
    #pragma unroll
    for (int q = 0; q < CC / 2; q++) {
        float a0, a1;
        unpack2(a0, a1, acc2[q]);
        ob[(2 * q + 0) * SS] = a0 + dcb[2 * q + 0];
        ob[(2 * q + 1) * SS] = a1 + dcb[2 * q + 1];
    }
}

// ---------------- launch: kernel launches ONLY ----------------
extern "C" void kernel_launch(void* const* d_in, const int* in_sizes, int n_in,
                              void* d_out, int out_size) {
    const float* x     = (const float*)d_in[0];
    const float* ln_s  = (const float*)d_in[1];
    const float* ln_b  = (const float*)d_in[2];
    const float* gamma = (const float*)d_in[3];
    const float* p1_w  = (const float*)d_in[4];
    const float* p1_b  = (const float*)d_in[5];
    const float* p2_w  = (const float*)d_in[6];
    const float* p2_b  = (const float*)d_in[7];
    const float* c0_w  = (const float*)d_in[8];
    const float* c0_b  = (const float*)d_in[9];
    const float* cs_w  = (const float*)d_in[10];
    const float* cs_b  = (const float*)d_in[11];
    const float* off_w = (const float*)d_in[12];
    const float* off_b = (const float*)d_in[13];
    const float* dc_w  = (const float*)d_in[14];
    const float* dc_b  = (const float*)d_in[15];
    const float* c1_w  = (const float*)d_in[16];
    const float* c1_b  = (const float*)d_in[17];
    const float* u1_w  = (const float*)d_in[18];
    const float* bn1_s = (const float*)d_in[19];
    const float* bn1_b = (const float*)d_in[20];
    const float* bn1_m = (const float*)d_in[21];
    const float* bn1_v = (const float*)d_in[22];
    const float* u2_w  = (const float*)d_in[23];
    const float* bn2_s = (const float*)d_in[24];
    const float* bn2_b = (const float*)d_in[25];
    const float* bn2_m = (const float*)d_in[26];
    const float* bn2_v = (const float*)d_in[27];
    const float* pr_w  = (const float*)d_in[28];
    const float* pr_b  = (const float*)d_in[29];
    float* out = (float*)d_out;

    dim3 pwGrid((BB * SS) / 256);
    dim3 dwGrid(SS / 256, CC, BB);
    dim3 c3OffGrid(SS / 256, 3, BB);   // 3 chunks of 27 output channels
    dim3 c3UGrid(SS / 256, 2, BB);     // 2 chunks of 24 output channels

    // 1. LayerNorm -> g_xn (0)
    k_ln<<<(BB * SS) / 256, 256>>>(x, ln_s, ln_b);
    // 2. proj_1 + GELU: g_xn -> g_u (1)
    k_pw48<<<pwGrid, 256>>>(0, nullptr, p1_w, p1_b, -1, nullptr, -1, nullptr,
                            1, nullptr, 0);
    // 3. depthwise 5x5x5 pad 2: g_u -> g_a1 (2)
    k_dw<5, 2, 1><<<dwGrid, 256>>>(1, c0_w, c0_b, 2);
    // 4. depthwise 7x7x7 dil 3 pad 9: g_a1 -> g_a2 (3)
    k_dw<7, 9, 3><<<dwGrid, 256>>>(2, cs_w, cs_b, 3);
    // 5. offset conv 3x3x3 -> 81 channels: g_a2 -> g_off (4)
    k_c3g<27, 28, 8><<<c3OffGrid, 256>>>(3, off_w, off_b,
                                         nullptr, nullptr, nullptr, nullptr,
                                         -1, 4, OFFC, 0);
    // 6. transpose deform weights
    k_wt<<<(CC * CC * 27 + 255) / 256, 256>>>(dc_w);
    // 7. deformable conv: (g_a2, g_off) -> g_a3 (5)
    k_deform<<<dim3(SS / 256, BB), 256>>>(dc_b);
    // 8. c1 1x1x1 + gate multiply: g_a3, aux g_u -> g_a1 (2, reuse)
    k_pw48<<<pwGrid, 256>>>(5, nullptr, c1_w, c1_b, 1, nullptr, -1, nullptr,
                            2, nullptr, 1);
    // 9. proj_2 + shortcut + gamma residual: g_a1, aux x, aux2 g_xn -> g_skip (6)
    k_pw48<<<pwGrid, 256>>>(2, nullptr, p2_w, p2_b, -1, x, 0, gamma,
                            6, nullptr, 2);
    // 10. u1 conv3 + BN1 + leaky: g_skip -> g_h1 (7)
    k_c3g<24, 24, 8><<<c3UGrid, 256>>>(6, u1_w, nullptr,
                                       bn1_s, bn1_b, bn1_m, bn1_v,
                                       -1, 7, CC, 1);
    // 11. u2 conv3 + BN2 + skip + leaky: g_h1 -> g_attn (8)
    k_c3g<24, 24, 8><<<c3UGrid, 256>>>(7, u2_w, nullptr,
                                       bn2_s, bn2_b, bn2_m, bn2_v,
                                       6, 8, CC, 2);
    // 12. projconv 1x1x1 + skip -> out (external)
    k_pw48<<<pwGrid, 256>>>(8, nullptr, pr_w, pr_b, 6, nullptr, -1, nullptr,
                            -1, out, 3);
}

// round 6
// speedup vs baseline: 3.7721x; 1.4652x over previous
#include <cuda_runtime.h>
#include <math.h>

// Problem constants (B=2, C=48, 32^3 volume)
#define BB   2
#define CC   48
#define SS   (32*32*32)          // 32768
#define OFFC 81

typedef unsigned long long ull;

// ---------------- f32x2 packed helpers (sm_100+) ----------------
__device__ __forceinline__ ull pack2(float a, float b) {
    ull r;
    asm("mov.b64 %0, {%1, %2};" : "=l"(r) : "f"(a), "f"(b));
    return r;
}
__device__ __forceinline__ void fma2(ull& d, ull a, ull b) {
    asm("fma.rn.f32x2 %0, %1, %2, %0;" : "+l"(d) : "l"(a), "l"(b));
}
__device__ __forceinline__ void unpack2(float& lo, float& hi, ull v) {
    asm("mov.b64 {%0, %1}, %2;" : "=f"(lo), "=f"(hi) : "l"(v));
}

// ---------------- scratch (device globals; allocation-free) ----------------
__device__ float g_xn  [BB*CC*SS];   // 0
__device__ float g_u   [BB*CC*SS];   // 1
__device__ float g_a1  [BB*CC*SS];   // 2
__device__ float g_a2  [BB*CC*SS];   // 3
__device__ float g_off [BB*OFFC*SS]; // 4
__device__ float g_a3  [BB*CC*SS];   // 5
__device__ float g_skip[BB*CC*SS];   // 6
__device__ float g_h1  [BB*CC*SS];   // 7
__device__ float g_attn[BB*CC*SS];   // 8
__device__ float g_dcwt[27*CC*CC];   // dc_w transposed to [tap][c][o]

__device__ __forceinline__ float* bufsel(int id, const float* ext) {
    switch (id) {
        case 0: return g_xn;   case 1: return g_u;    case 2: return g_a1;
        case 3: return g_a2;   case 4: return g_off;  case 5: return g_a3;
        case 6: return g_skip; case 7: return g_h1;   case 8: return g_attn;
    }
    return (float*)ext;
}

// ---------------- LayerNorm over C per voxel ----------------
__global__ void k_ln(const float* __restrict__ x,
                     const float* __restrict__ ls,
                     const float* __restrict__ lb) {
    int i = blockIdx.x * blockDim.x + threadIdx.x;
    if (i >= BB * SS) return;
    int b = i >> 15, s = i & (SS - 1);
    const float* xb = x + (size_t)b * CC * SS + s;
    float v[CC];
    float mu = 0.f;
    #pragma unroll
    for (int c = 0; c < CC; c++) { v[c] = xb[c * SS]; mu += v[c]; }
    mu *= (1.f / CC);
    float var = 0.f;
    #pragma unroll
    for (int c = 0; c < CC; c++) { float d = v[c] - mu; var += d * d; }
    var *= (1.f / CC);
    float inv = rsqrtf(var + 1e-5f);
    float* ob = g_xn + (size_t)b * CC * SS + s;
    #pragma unroll
    for (int c = 0; c < CC; c++)
        ob[c * SS] = (v[c] - mu) * inv * ls[c] + lb[c];
}

// ---------------- 1x1x1 pointwise 48x48, f32x2 output pairs ----------------
// mode 0: gelu; 1: gate mult; 2: skip+gamma residual; 3: skip add
__global__ void __launch_bounds__(256) k_pw48(
    int in_id, const float* __restrict__ ext_in,
    const float* __restrict__ w, const float* __restrict__ bias,
    int a1_id, const float* __restrict__ ext_a1,
    int a2_id,
    const float* __restrict__ gamma,
    int out_id, float* __restrict__ ext_out,
    int mode)
{
    __shared__ __align__(16) float ws2[CC * CC];   // [c][o], o contiguous
    __shared__ float bs[CC];
    for (int i = threadIdx.x; i < CC * CC; i += blockDim.x) {
        int o = i / CC, c = i - o * CC;
        ws2[c * CC + o] = w[i];
    }
    if (threadIdx.x < CC) bs[threadIdx.x] = bias[threadIdx.x];
    __syncthreads();

    int i = blockIdx.x * blockDim.x + threadIdx.x;
    int b = i >> 15, s = i & (SS - 1);
    const float* in = bufsel(in_id, ext_in) + (size_t)b * CC * SS + s;

    ull acc2[CC / 2];
    #pragma unroll
    for (int q = 0; q < CC / 2; q++) acc2[q] = 0ull;

    const ulonglong2* wrow = (const ulonglong2*)ws2;
    #pragma unroll 4
    for (int c = 0; c < CC; c++) {
        float v = in[c * SS];
        ull vv = pack2(v, v);
        #pragma unroll
        for (int q = 0; q < CC / 4; q++) {
            ulonglong2 wq = wrow[c * (CC / 4) + q];
            fma2(acc2[2 * q + 0], wq.x, vv);
            fma2(acc2[2 * q + 1], wq.y, vv);
        }
    }

    float acc[CC];
    #pragma unroll
    for (int q = 0; q < CC / 2; q++) unpack2(acc[2 * q], acc[2 * q + 1], acc2[q]);

    size_t base = (size_t)b * CC * SS + s;
    float* outp = bufsel(out_id, (const float*)ext_out) + base;
    const float* a1p = bufsel(a1_id, ext_a1) + base;
    const float* a2p = g_xn + base;

    if (mode == 0) {
        #pragma unroll
        for (int o = 0; o < CC; o++) {
            float v = acc[o] + bs[o];
            outp[o * SS] = 0.5f * v * (1.f + erff(v * 0.70710678118654752f));
        }
    } else if (mode == 1) {
        #pragma unroll
        for (int o = 0; o < CC; o++)
            outp[o * SS] = a1p[o * SS] * (acc[o] + bs[o]);
    } else if (mode == 2) {
        #pragma unroll
        for (int o = 0; o < CC; o++)
            outp[o * SS] = a1p[o * SS] + gamma[o] * (acc[o] + bs[o] + a2p[o * SS]);
    } else {
        #pragma unroll
        for (int o = 0; o < CC; o++)
            outp[o * SS] = a1p[o * SS] + acc[o] + bs[o];
    }
}

// ---------------- depthwise KxKxK: 4 x-adjacent outputs/thread, float4 rows ----------------
// Thread handles outputs x0..x0+3 (x0 multiple of 4). Per valid (z,y) row we load
// the needed x-window as aligned float4 chunks; each chunk is provably fully in-
// or out-of-bounds (one predicate), OOB chunks load 0 which zeroes invalid taps.
// All tap->register indices are compile-time constants.
template<int K, int PAD, int DIL>
__global__ void __launch_bounds__(256) k_dw(int in_id, const float* __restrict__ w,
                                            const float* __restrict__ bias, int out_id) {
    constexpr int LOW = -(((PAD) + 3) / 4) * 4;           // chunk-aligned lower bound
    constexpr int HI  = 3 + (K - 1) * DIL - PAD;          // highest needed offset
    constexpr int NCH = (HI - LOW) / 4 + 1;               // float4 chunks per row
    __shared__ float ws[K * K * K];
    int c = blockIdx.y, b = blockIdx.z;
    for (int i = threadIdx.x; i < K * K * K; i += blockDim.x)
        ws[i] = w[c * K * K * K + i];
    __syncthreads();
    int s = blockIdx.x * 1024 + threadIdx.x * 4;
    int z = s >> 10, y = (s >> 5) & 31, x0 = s & 31;
    const float* ib = bufsel(in_id, nullptr) + ((size_t)b * CC + c) * SS;

    float b0 = bias[c];
    float acc[4] = {b0, b0, b0, b0};

    #pragma unroll
    for (int i = 0; i < K; i++) {
        int zz = z + i * DIL - PAD;
        if ((unsigned)zz >= 32u) continue;
        #pragma unroll
        for (int j = 0; j < K; j++) {
            int yy = y + j * DIL - PAD;
            if ((unsigned)yy >= 32u) continue;
            const float* row = ib + (zz << 10) + (yy << 5);
            float v[NCH * 4];
            #pragma unroll
            for (int ch = 0; ch < NCH; ch++) {
                int xb = x0 + LOW + ch * 4;
                if (xb >= 0 && xb <= 28) {
                    float4 t = *(const float4*)(row + xb);
                    v[ch * 4 + 0] = t.x; v[ch * 4 + 1] = t.y;
                    v[ch * 4 + 2] = t.z; v[ch * 4 + 3] = t.w;
                } else {
                    v[ch * 4 + 0] = 0.f; v[ch * 4 + 1] = 0.f;
                    v[ch * 4 + 2] = 0.f; v[ch * 4 + 3] = 0.f;
                }
            }
            const float* wr = ws + (i * K + j) * K;
            #pragma unroll
            for (int l = 0; l < K; l++) {
                float wv = wr[l];
                #pragma unroll
                for (int u = 0; u < 4; u++)
                    acc[u] += wv * v[u + l * DIL - PAD - LOW];
            }
        }
    }
    float* op = bufsel(out_id, nullptr) + ((size_t)b * CC + c) * SS + s;
    *(float4*)op = make_float4(acc[0], acc[1], acc[2], acc[3]);
}

// ---------------- dense 3x3x3 conv, 2 x-adjacent voxels/thread, f32x2 ----------------
// Weight smem layout [cL][tap][o] (NO4 floats). The two voxels share every weight
// LDS.128 and 18 of the 27 neighborhood values (36-value window per channel).
// mode 0: +bias; 1: leaky(bn); 2: leaky(bn + skip)
template<int NO, int NO4, int CCH>
__global__ void __launch_bounds__(256) k_c3g(
    int in_id, const float* __restrict__ w,
    const float* __restrict__ bias,
    const float* __restrict__ bs2, const float* __restrict__ bbp,
    const float* __restrict__ bm, const float* __restrict__ bv,
    int skip_id, int out_id, int O, int mode)
{
    __shared__ __align__(16) float ws[CCH * 27 * NO4];
    const int o0 = blockIdx.y * NO;
    const int b  = blockIdx.z;
    const int s  = blockIdx.x * 512 + threadIdx.x * 2;   // voxels s, s+1
    const int z = s >> 10, y = (s >> 5) & 31, x0 = s & 31;
    const float* ib = bufsel(in_id, nullptr) + (size_t)b * CC * SS;

    ull accA[NO4 / 2], accB[NO4 / 2];
    #pragma unroll
    for (int q = 0; q < NO4 / 2; q++) { accA[q] = 0ull; accB[q] = 0ull; }

    for (int cbase = 0; cbase < CC; cbase += CCH) {
        __syncthreads();
        for (int gidx = threadIdx.x; gidx < NO * CCH * 27; gidx += blockDim.x) {
            int oL  = gidx / (CCH * 27);
            int r   = gidx - oL * (CCH * 27);
            int cL  = r / 27;
            int tap = r - cL * 27;
            ws[(cL * 27 + tap) * NO4 + oL] =
                w[(size_t)(o0 + oL) * (CC * 27) + (cbase + cL) * 27 + tap];
        }
        __syncthreads();

        for (int cL = 0; cL < CCH; cL++) {
            const float* ic = ib + (cbase + cL) * SS;
            float v[36];   // 9 rows x 4 x-values (x0-1 .. x0+2)
            #pragma unroll
            for (int kd = 0; kd < 3; kd++) {
                int zz = z + kd - 1; bool vz = (unsigned)zz < 32u;
                #pragma unroll
                for (int kh = 0; kh < 3; kh++) {
                    int yy = y + kh - 1; bool vy = (unsigned)yy < 32u;
                    int base = (zz << 10) + (yy << 5);
                    #pragma unroll
                    for (int xo = 0; xo < 4; xo++) {
                        int xx = x0 - 1 + xo;
                        bool ok = vz && vy && ((unsigned)xx < 32u);
                        v[(kd * 3 + kh) * 4 + xo] = ok ? ic[base + xx] : 0.f;
                    }
                }
            }
            const ulonglong2* wrow = (const ulonglong2*)(ws + cL * 27 * NO4);
            #pragma unroll
            for (int tap = 0; tap < 27; tap++) {
                int r  = tap / 3;      // (kd*3+kh)
                int kw = tap - r * 3;
                float vA = v[r * 4 + kw];
                float vB = v[r * 4 + kw + 1];
                ull vvA = pack2(vA, vA);
                ull vvB = pack2(vB, vB);
                #pragma unroll
                for (int q = 0; q < NO4 / 4; q++) {
                    ulonglong2 wq = wrow[tap * (NO4 / 4) + q];
                    fma2(accA[2 * q + 0], wq.x, vvA);
                    fma2(accA[2 * q + 1], wq.y, vvA);
                    fma2(accB[2 * q + 0], wq.x, vvB);
                    fma2(accB[2 * q + 1], wq.y, vvB);
                }
            }
        }
    }

    float aA[NO4], aB[NO4];
    #pragma unroll
    for (int q = 0; q < NO4 / 2; q++) {
        unpack2(aA[2 * q], aA[2 * q + 1], accA[q]);
        unpack2(aB[2 * q], aB[2 * q + 1], accB[q]);
    }

    float* outb = bufsel(out_id, nullptr) + (size_t)b * O * SS + s;
    if (mode == 0) {
        #pragma unroll
        for (int o = 0; o < NO; o++) {
            float bb = bias[o0 + o];
            *(float2*)&outb[(o0 + o) * SS] = make_float2(aA[o] + bb, aB[o] + bb);
        }
    } else {
        const float* skp = (mode == 2) ? bufsel(skip_id, nullptr) + (size_t)b * O * SS + s
                                       : nullptr;
        #pragma unroll
        for (int o = 0; o < NO; o++) {
            int og = o0 + o;
            float scale = bs2[og] * rsqrtf(bv[og] + 1e-5f);
            float sh = bbp[og] - bm[og] * scale;
            float hA = aA[o] * scale + sh;
            float hB = aB[o] * scale + sh;
            if (mode == 2) { hA += skp[og * SS]; hB += skp[og * SS + 1]; }
            hA = (hA >= 0.f) ? hA : 0.01f * hA;
            hB = (hB >= 0.f) ? hB : 0.01f * hB;
            *(float2*)&outb[og * SS] = make_float2(hA, hB);
        }
    }
}

// ---------------- transpose dc_w [o][c][k] -> [k][c][o] ----------------
__global__ void k_wt(const float* __restrict__ w) {
    int i = blockIdx.x * blockDim.x + threadIdx.x;
    if (i >= CC * CC * 27) return;
    int o = i / (CC * 27);
    int r = i - o * (CC * 27);
    int c = r / 27;
    int k = r - c * 27;
    g_dcwt[(k * CC + c) * CC + o] = w[i];
}

// ---------------- deformable conv: smem weight staging + f32x2 ----------------
__global__ void __launch_bounds__(256) k_deform(const float* __restrict__ dcb) {
    __shared__ __align__(16) float wt_s[CC * CC];   // [c][o] for current tap
    int s = blockIdx.x * blockDim.x + threadIdx.x;
    int b = blockIdx.y;
    int z = s >> 10, y = (s >> 5) & 31, x = s & 31;
    const float* a   = g_a2  + (size_t)b * CC * SS;
    const float* off = g_off + (size_t)b * OFFC * SS + s;

    ull acc2[CC / 2];
    #pragma unroll
    for (int q = 0; q < CC / 2; q++) acc2[q] = 0ull;

    int k = 0;
    #pragma unroll 1
    for (int kd = -1; kd <= 1; kd++)
    for (int kh = -1; kh <= 1; kh++)
    for (int kw = -1; kw <= 1; kw++) {
        __syncthreads();
        {
            const float4* src = (const float4*)(g_dcwt + k * CC * CC);
            float4* dst = (float4*)wt_s;
            for (int i = threadIdx.x; i < CC * CC / 4; i += blockDim.x)
                dst[i] = src[i];
        }
        __syncthreads();

        float zf = (float)(z + kd) + off[(k * 3 + 0) * SS];
        float yf = (float)(y + kh) + off[(k * 3 + 1) * SS];
        float xf = (float)(x + kw) + off[(k * 3 + 2) * SS];
        float z0 = floorf(zf), y0 = floorf(yf), x0 = floorf(xf);
        float tz = zf - z0, ty = yf - y0, tx = xf - x0;
        int iz0 = (int)z0, iy0 = (int)y0, ix0 = (int)x0;

        int idx8[8];
        ull w8v[8];
        #pragma unroll
        for (int dz = 0; dz < 2; dz++)
        #pragma unroll
        for (int dy = 0; dy < 2; dy++)
        #pragma unroll
        for (int dx = 0; dx < 2; dx++) {
            int j = dz * 4 + dy * 2 + dx;
            int zi = iz0 + dz, yi = iy0 + dy, xi = ix0 + dx;
            bool valid = (zi >= 0 && zi < 32 && yi >= 0 && yi < 32 && xi >= 0 && xi < 32);
            float wg = (dz ? tz : 1.f - tz) * (dy ? ty : 1.f - ty) * (dx ? tx : 1.f - tx);
            int zc = min(max(zi, 0), 31), yc = min(max(yi, 0), 31), xc = min(max(xi, 0), 31);
            idx8[j] = (zc << 10) + (yc << 5) + xc;
            float wf = valid ? wg : 0.f;
            w8v[j] = pack2(wf, wf);
        }

        for (int c = 0; c < CC; c += 2) {
            const float* ac0 = a + c * SS;
            const float* ac1 = ac0 + SS;
            ull valv = 0ull;
            #pragma unroll
            for (int j = 0; j < 8; j++)
                fma2(valv, pack2(ac0[idx8[j]], ac1[idx8[j]]), w8v[j]);
            float v0, v1;
            unpack2(v0, v1, valv);
            ull vv0 = pack2(v0, v0), vv1 = pack2(v1, v1);

            const ulonglong2* w0 = (const ulonglong2*)(wt_s + (c + 0) * CC);
            const ulonglong2* w1 = (const ulonglong2*)(wt_s + (c + 1) * CC);
            #pragma unroll
            for (int q = 0; q < CC / 4; q++) {
                ulonglong2 wa = w0[q];
                fma2(acc2[2 * q + 0], wa.x, vv0);
                fma2(acc2[2 * q + 1], wa.y, vv0);
            }
            #pragma unroll
            for (int q = 0; q < CC / 4; q++) {
                ulonglong2 wb = w1[q];
                fma2(acc2[2 * q + 0], wb.x, vv1);
                fma2(acc2[2 * q + 1], wb.y, vv1);
            }
        }
        k++;
    }

    float* ob = g_a3 + (size_t)b * CC * SS + s;
    #pragma unroll
    for (int q = 0; q < CC / 2; q++) {
        float a0, a1;
        unpack2(a0, a1, acc2[q]);
        ob[(2 * q + 0) * SS] = a0 + dcb[2 * q + 0];
        ob[(2 * q + 1) * SS] = a1 + dcb[2 * q + 1];
    }
}

// ---------------- launch: kernel launches ONLY ----------------
extern "C" void kernel_launch(void* const* d_in, const int* in_sizes, int n_in,
                              void* d_out, int out_size) {
    const float* x     = (const float*)d_in[0];
    const float* ln_s  = (const float*)d_in[1];
    const float* ln_b  = (const float*)d_in[2];
    const float* gamma = (const float*)d_in[3];
    const float* p1_w  = (const float*)d_in[4];
    const float* p1_b  = (const float*)d_in[5];
    const float* p2_w  = (const float*)d_in[6];
    const float* p2_b  = (const float*)d_in[7];
    const float* c0_w  = (const float*)d_in[8];
    const float* c0_b  = (const float*)d_in[9];
    const float* cs_w  = (const float*)d_in[10];
    const float* cs_b  = (const float*)d_in[11];
    const float* off_w = (const float*)d_in[12];
    const float* off_b = (const float*)d_in[13];
    const float* dc_w  = (const float*)d_in[14];
    const float* dc_b  = (const float*)d_in[15];
    const float* c1_w  = (const float*)d_in[16];
    const float* c1_b  = (const float*)d_in[17];
    const float* u1_w  = (const float*)d_in[18];
    const float* bn1_s = (const float*)d_in[19];
    const float* bn1_b = (const float*)d_in[20];
    const float* bn1_m = (const float*)d_in[21];
    const float* bn1_v = (const float*)d_in[22];
    const float* u2_w  = (const float*)d_in[23];
    const float* bn2_s = (const float*)d_in[24];
    const float* bn2_b = (const float*)d_in[25];
    const float* bn2_m = (const float*)d_in[26];
    const float* bn2_v = (const float*)d_in[27];
    const float* pr_w  = (const float*)d_in[28];
    const float* pr_b  = (const float*)d_in[29];
    float* out = (float*)d_out;

    dim3 pwGrid((BB * SS) / 256);
    dim3 dwGrid(SS / 1024, CC, BB);    // 4 voxels per thread
    dim3 c3OffGrid(SS / 512, 3, BB);   // 2 voxels/thread, 3 chunks of 27 outputs
    dim3 c3UGrid(SS / 512, 2, BB);     // 2 voxels/thread, 2 chunks of 24 outputs

    // 1. LayerNorm -> g_xn (0)
    k_ln<<<(BB * SS) / 256, 256>>>(x, ln_s, ln_b);
    // 2. proj_1 + GELU: g_xn -> g_u (1)
    k_pw48<<<pwGrid, 256>>>(0, nullptr, p1_w, p1_b, -1, nullptr, -1, nullptr,
                            1, nullptr, 0);
    // 3. depthwise 5x5x5 pad 2: g_u -> g_a1 (2)
    k_dw<5, 2, 1><<<dwGrid, 256>>>(1, c0_w, c0_b, 2);
    // 4. depthwise 7x7x7 dil 3 pad 9: g_a1 -> g_a2 (3)
    k_dw<7, 9, 3><<<dwGrid, 256>>>(2, cs_w, cs_b, 3);
    // 5. offset conv 3x3x3 -> 81 channels: g_a2 -> g_off (4)
    k_c3g<27, 28, 8><<<c3OffGrid, 256>>>(3, off_w, off_b,
                                         nullptr, nullptr, nullptr, nullptr,
                                         -1, 4, OFFC, 0);
    // 6. transpose deform weights
    k_wt<<<(CC * CC * 27 + 255) / 256, 256>>>(dc_w);
    // 7. deformable conv: (g_a2, g_off) -> g_a3 (5)
    k_deform<<<dim3(SS / 256, BB), 256>>>(dc_b);
    // 8. c1 1x1x1 + gate multiply: g_a3, aux g_u -> g_a1 (2, reuse)
    k_pw48<<<pwGrid, 256>>>(5, nullptr, c1_w, c1_b, 1, nullptr, -1, nullptr,
                            2, nullptr, 1);
    // 9. proj_2 + shortcut + gamma residual: g_a1, aux x, aux2 g_xn -> g_skip (6)
    k_pw48<<<pwGrid, 256>>>(2, nullptr, p2_w, p2_b, -1, x, 0, gamma,
                            6, nullptr, 2);
    // 10. u1 conv3 + BN1 + leaky: g_skip -> g_h1 (7)
    k_c3g<24, 24, 8><<<c3UGrid, 256>>>(6, u1_w, nullptr,
                                       bn1_s, bn1_b, bn1_m, bn1_v,
                                       -1, 7, CC, 1);
    // 11. u2 conv3 + BN2 + skip + leaky: g_h1 -> g_attn (8)
    k_c3g<24, 24, 8><<<c3UGrid, 256>>>(7, u2_w, nullptr,
                                       bn2_s, bn2_b, bn2_m, bn2_v,
                                       6, 8, CC, 2);
    // 12. projconv 1x1x1 + skip -> out (external)
    k_pw48<<<pwGrid, 256>>>(8, nullptr, pr_w, pr_b, 6, nullptr, -1, nullptr,
                            -1, out, 3);
}

// round 8
// speedup vs baseline: 3.8476x; 1.0200x over previous
#include <cuda_runtime.h>
#include <math.h>

// Problem constants (B=2, C=48, 32^3 volume)
#define BB   2
#define CC   48
#define SS   (32*32*32)          // 32768
#define OFFC 81

typedef unsigned long long ull;

// ---------------- f32x2 packed helpers (sm_100+) ----------------
__device__ __forceinline__ ull pack2(float a, float b) {
    ull r;
    asm("mov.b64 %0, {%1, %2};" : "=l"(r) : "f"(a), "f"(b));
    return r;
}
__device__ __forceinline__ void fma2(ull& d, ull a, ull b) {
    asm("fma.rn.f32x2 %0, %1, %2, %0;" : "+l"(d) : "l"(a), "l"(b));
}
__device__ __forceinline__ void unpack2(float& lo, float& hi, ull v) {
    asm("mov.b64 {%0, %1}, %2;" : "=f"(lo), "=f"(hi) : "l"(v));
}

// ---------------- scratch (device globals; allocation-free) ----------------
__device__ float g_xn  [BB*CC*SS];   // 0
__device__ float g_u   [BB*CC*SS];   // 1
__device__ float g_a1  [BB*CC*SS];   // 2
__device__ float g_a2  [BB*CC*SS];   // 3
__device__ float g_off [BB*OFFC*SS]; // 4
__device__ float g_a3  [BB*CC*SS];   // 5  (deform partial 0)
__device__ float g_skip[BB*CC*SS];   // 6
__device__ float g_h1  [BB*CC*SS];   // 7  (deform partial 1, later u1 out)
__device__ float g_attn[BB*CC*SS];   // 8  (deform partial 2, later u2 out)
__device__ float g_dcwt[27*CC*CC];   // dc_w transposed to [tap][c][o]

__device__ __forceinline__ float* bufsel(int id, const float* ext) {
    switch (id) {
        case 0: return g_xn;   case 1: return g_u;    case 2: return g_a1;
        case 3: return g_a2;   case 4: return g_off;  case 5: return g_a3;
        case 6: return g_skip; case 7: return g_h1;   case 8: return g_attn;
    }
    return (float*)ext;
}

// ---------------- fused LayerNorm + proj_1 + GELU ----------------
// pass1: mean/var from streaming loads; pass2: normalize (write g_xn) + GEMM -> gelu -> g_u
__global__ void __launch_bounds__(256) k_lnpw(
    const float* __restrict__ x,
    const float* __restrict__ ls, const float* __restrict__ lb,
    const float* __restrict__ w,  const float* __restrict__ bias)
{
    __shared__ __align__(16) float ws2[CC * CC];   // [c][o], o contiguous
    __shared__ float bs[CC];
    for (int i = threadIdx.x; i < CC * CC; i += blockDim.x) {
        int o = i / CC, c = i - o * CC;
        ws2[c * CC + o] = w[i];
    }
    if (threadIdx.x < CC) bs[threadIdx.x] = bias[threadIdx.x];
    __syncthreads();

    int i = blockIdx.x * blockDim.x + threadIdx.x;
    int b = i >> 15, s = i & (SS - 1);
    const float* xb = x + (size_t)b * CC * SS + s;

    float s1 = 0.f, s2 = 0.f;
    #pragma unroll 8
    for (int c = 0; c < CC; c++) { float v = xb[c * SS]; s1 += v; s2 += v * v; }
    float mu  = s1 * (1.f / CC);
    float var = s2 * (1.f / CC) - mu * mu;
    float inv = rsqrtf(var + 1e-5f);

    float* xnp = g_xn + (size_t)b * CC * SS + s;

    ull acc2[CC / 2];
    #pragma unroll
    for (int q = 0; q < CC / 2; q++) acc2[q] = 0ull;

    const ulonglong2* wrow = (const ulonglong2*)ws2;
    #pragma unroll 4
    for (int c = 0; c < CC; c++) {
        float v = (xb[c * SS] - mu) * inv * ls[c] + lb[c];
        xnp[c * SS] = v;
        ull vv = pack2(v, v);
        #pragma unroll
        for (int q = 0; q < CC / 4; q++) {
            ulonglong2 wq = wrow[c * (CC / 4) + q];
            fma2(acc2[2 * q + 0], wq.x, vv);
            fma2(acc2[2 * q + 1], wq.y, vv);
        }
    }

    float* up = g_u + (size_t)b * CC * SS + s;
    #pragma unroll
    for (int q = 0; q < CC / 2; q++) {
        float a0, a1;
        unpack2(a0, a1, acc2[q]);
        float v0 = a0 + bs[2 * q + 0];
        float v1 = a1 + bs[2 * q + 1];
        up[(2 * q + 0) * SS] = 0.5f * v0 * (1.f + erff(v0 * 0.70710678118654752f));
        up[(2 * q + 1) * SS] = 0.5f * v1 * (1.f + erff(v1 * 0.70710678118654752f));
    }
}

// ---------------- 1x1x1 pointwise 48x48, f32x2 output pairs ----------------
// mode 1: out = aux1 * (acc + bias[o]); input = a3+h1+attn partials + dcb[c]
// mode 2: out = aux1 + gamma[o]*(acc + bias[o] + g_xn)
// mode 3: out = aux1 + acc + bias[o]
__global__ void __launch_bounds__(256) k_pw48(
    int in_id, const float* __restrict__ ext_in,
    const float* __restrict__ w, const float* __restrict__ bias,
    int a1_id, const float* __restrict__ ext_a1,
    const float* __restrict__ gamma,
    const float* __restrict__ dcb,
    int out_id, float* __restrict__ ext_out,
    int mode)
{
    __shared__ __align__(16) float ws2[CC * CC];   // [c][o], o contiguous
    __shared__ float bs[CC];
    __shared__ float dcs[CC];
    for (int i = threadIdx.x; i < CC * CC; i += blockDim.x) {
        int o = i / CC, c = i - o * CC;
        ws2[c * CC + o] = w[i];
    }
    if (threadIdx.x < CC) {
        bs[threadIdx.x] = bias[threadIdx.x];
        dcs[threadIdx.x] = (dcb != nullptr) ? dcb[threadIdx.x] : 0.f;
    }
    __syncthreads();

    int i = blockIdx.x * blockDim.x + threadIdx.x;
    int b = i >> 15, s = i & (SS - 1);
    size_t base = (size_t)b * CC * SS + s;
    const float* in = bufsel(in_id, ext_in) + base;
    const float* pp1 = g_h1 + base;    // deform partial 1 (mode 1 only)
    const float* pp2 = g_attn + base;  // deform partial 2 (mode 1 only)

    ull acc2[CC / 2];
    #pragma unroll
    for (int q = 0; q < CC / 2; q++) acc2[q] = 0ull;

    const ulonglong2* wrow = (const ulonglong2*)ws2;
    if (mode == 1) {
        #pragma unroll 4
        for (int c = 0; c < CC; c++) {
            float v = in[c * SS] + pp1[c * SS] + pp2[c * SS] + dcs[c];
            ull vv = pack2(v, v);
            #pragma unroll
            for (int q = 0; q < CC / 4; q++) {
                ulonglong2 wq = wrow[c * (CC / 4) + q];
                fma2(acc2[2 * q + 0], wq.x, vv);
                fma2(acc2[2 * q + 1], wq.y, vv);
            }
        }
    } else {
        #pragma unroll 4
        for (int c = 0; c < CC; c++) {
            float v = in[c * SS];
            ull vv = pack2(v, v);
            #pragma unroll
            for (int q = 0; q < CC / 4; q++) {
                ulonglong2 wq = wrow[c * (CC / 4) + q];
                fma2(acc2[2 * q + 0], wq.x, vv);
                fma2(acc2[2 * q + 1], wq.y, vv);
            }
        }
    }

    float acc[CC];
    #pragma unroll
    for (int q = 0; q < CC / 2; q++) unpack2(acc[2 * q], acc[2 * q + 1], acc2[q]);

    float* outp = bufsel(out_id, (const float*)ext_out) + base;
    const float* a1p = bufsel(a1_id, ext_a1) + base;
    const float* a2p = g_xn + base;

    if (mode == 1) {
        #pragma unroll
        for (int o = 0; o < CC; o++)
            outp[o * SS] = a1p[o * SS] * (acc[o] + bs[o]);
    } else if (mode == 2) {
        #pragma unroll
        for (int o = 0; o < CC; o++)
            outp[o * SS] = a1p[o * SS] + gamma[o] * (acc[o] + bs[o] + a2p[o * SS]);
    } else {
        #pragma unroll
        for (int o = 0; o < CC; o++)
            outp[o * SS] = a1p[o * SS] + acc[o] + bs[o];
    }
}

// ---------------- depthwise KxKxK: 4 x-adjacent outputs/thread, float4 rows ----------------
template<int K, int PAD, int DIL>
__global__ void __launch_bounds__(256) k_dw(int in_id, const float* __restrict__ w,
                                            const float* __restrict__ bias, int out_id) {
    constexpr int LOW = -(((PAD) + 3) / 4) * 4;
    constexpr int HI  = 3 + (K - 1) * DIL - PAD;
    constexpr int NCH = (HI - LOW) / 4 + 1;
    __shared__ float ws[K * K * K];
    int c = blockIdx.y, b = blockIdx.z;
    for (int i = threadIdx.x; i < K * K * K; i += blockDim.x)
        ws[i] = w[c * K * K * K + i];
    __syncthreads();
    int s = blockIdx.x * 1024 + threadIdx.x * 4;
    int z = s >> 10, y = (s >> 5) & 31, x0 = s & 31;
    const float* ib = bufsel(in_id, nullptr) + ((size_t)b * CC + c) * SS;

    float b0 = bias[c];
    float acc[4] = {b0, b0, b0, b0};

    #pragma unroll
    for (int i = 0; i < K; i++) {
        int zz = z + i * DIL - PAD;
        if ((unsigned)zz >= 32u) continue;
        #pragma unroll
        for (int j = 0; j < K; j++) {
            int yy = y + j * DIL - PAD;
            if ((unsigned)yy >= 32u) continue;
            const float* row = ib + (zz << 10) + (yy << 5);
            float v[NCH * 4];
            #pragma unroll
            for (int ch = 0; ch < NCH; ch++) {
                int xb = x0 + LOW + ch * 4;
                if (xb >= 0 && xb <= 28) {
                    float4 t = *(const float4*)(row + xb);
                    v[ch * 4 + 0] = t.x; v[ch * 4 + 1] = t.y;
                    v[ch * 4 + 2] = t.z; v[ch * 4 + 3] = t.w;
                } else {
                    v[ch * 4 + 0] = 0.f; v[ch * 4 + 1] = 0.f;
                    v[ch * 4 + 2] = 0.f; v[ch * 4 + 3] = 0.f;
                }
            }
            const float* wr = ws + (i * K + j) * K;
            #pragma unroll
            for (int l = 0; l < K; l++) {
                float wv = wr[l];
                #pragma unroll
                for (int u = 0; u < 4; u++)
                    acc[u] += wv * v[u + l * DIL - PAD - LOW];
            }
        }
    }
    float* op = bufsel(out_id, nullptr) + ((size_t)b * CC + c) * SS + s;
    *(float4*)op = make_float4(acc[0], acc[1], acc[2], acc[3]);
}

// ---------------- dense 3x3x3 conv, 2 x-adjacent voxels/thread, f32x2 ----------------
template<int NO, int NO4, int CCH>
__global__ void __launch_bounds__(256) k_c3g(
    int in_id, const float* __restrict__ w,
    const float* __restrict__ bias,
    const float* __restrict__ bs2, const float* __restrict__ bbp,
    const float* __restrict__ bm, const float* __restrict__ bv,
    int skip_id, int out_id, int O, int mode)
{
    __shared__ __align__(16) float ws[CCH * 27 * NO4];
    const int o0 = blockIdx.y * NO;
    const int b  = blockIdx.z;
    const int s  = blockIdx.x * 512 + threadIdx.x * 2;
    const int z = s >> 10, y = (s >> 5) & 31, x0 = s & 31;
    const float* ib = bufsel(in_id, nullptr) + (size_t)b * CC * SS;

    ull accA[NO4 / 2], accB[NO4 / 2];
    #pragma unroll
    for (int q = 0; q < NO4 / 2; q++) { accA[q] = 0ull; accB[q] = 0ull; }

    for (int cbase = 0; cbase < CC; cbase += CCH) {
        __syncthreads();
        for (int gidx = threadIdx.x; gidx < NO * CCH * 27; gidx += blockDim.x) {
            int oL  = gidx / (CCH * 27);
            int r   = gidx - oL * (CCH * 27);
            int cL  = r / 27;
            int tap = r - cL * 27;
            ws[(cL * 27 + tap) * NO4 + oL] =
                w[(size_t)(o0 + oL) * (CC * 27) + (cbase + cL) * 27 + tap];
        }
        __syncthreads();

        for (int cL = 0; cL < CCH; cL++) {
            const float* ic = ib + (cbase + cL) * SS;
            float v[36];
            #pragma unroll
            for (int kd = 0; kd < 3; kd++) {
                int zz = z + kd - 1; bool vz = (unsigned)zz < 32u;
                #pragma unroll
                for (int kh = 0; kh < 3; kh++) {
                    int yy = y + kh - 1; bool vy = (unsigned)yy < 32u;
                    int base = (zz << 10) + (yy << 5);
                    #pragma unroll
                    for (int xo = 0; xo < 4; xo++) {
                        int xx = x0 - 1 + xo;
                        bool ok = vz && vy && ((unsigned)xx < 32u);
                        v[(kd * 3 + kh) * 4 + xo] = ok ? ic[base + xx] : 0.f;
                    }
                }
            }
            const ulonglong2* wrow = (const ulonglong2*)(ws + cL * 27 * NO4);
            #pragma unroll
            for (int tap = 0; tap < 27; tap++) {
                int r  = tap / 3;
                int kw = tap - r * 3;
                float vA = v[r * 4 + kw];
                float vB = v[r * 4 + kw + 1];
                ull vvA = pack2(vA, vA);
                ull vvB = pack2(vB, vB);
                #pragma unroll
                for (int q = 0; q < NO4 / 4; q++) {
                    ulonglong2 wq = wrow[tap * (NO4 / 4) + q];
                    fma2(accA[2 * q + 0], wq.x, vvA);
                    fma2(accA[2 * q + 1], wq.y, vvA);
                    fma2(accB[2 * q + 0], wq.x, vvB);
                    fma2(accB[2 * q + 1], wq.y, vvB);
                }
            }
        }
    }

    float aA[NO4], aB[NO4];
    #pragma unroll
    for (int q = 0; q < NO4 / 2; q++) {
        unpack2(aA[2 * q], aA[2 * q + 1], accA[q]);
        unpack2(aB[2 * q], aB[2 * q + 1], accB[q]);
    }

    float* outb = bufsel(out_id, nullptr) + (size_t)b * O * SS + s;
    if (mode == 0) {
        #pragma unroll
        for (int o = 0; o < NO; o++) {
            float bb = bias[o0 + o];
            *(float2*)&outb[(o0 + o) * SS] = make_float2(aA[o] + bb, aB[o] + bb);
        }
    } else {
        const float* skp = (mode == 2) ? bufsel(skip_id, nullptr) + (size_t)b * O * SS + s
                                       : nullptr;
        #pragma unroll
        for (int o = 0; o < NO; o++) {
            int og = o0 + o;
            float scale = bs2[og] * rsqrtf(bv[og] + 1e-5f);
            float sh = bbp[og] - bm[og] * scale;
            float hA = aA[o] * scale + sh;
            float hB = aB[o] * scale + sh;
            if (mode == 2) { hA += skp[og * SS]; hB += skp[og * SS + 1]; }
            hA = (hA >= 0.f) ? hA : 0.01f * hA;
            hB = (hB >= 0.f) ? hB : 0.01f * hB;
            *(float2*)&outb[og * SS] = make_float2(hA, hB);
        }
    }
}

// ---------------- transpose dc_w [o][c][k] -> [k][c][o] ----------------
__global__ void k_wt(const float* __restrict__ w) {
    int i = blockIdx.x * blockDim.x + threadIdx.x;
    if (i >= CC * CC * 27) return;
    int o = i / (CC * 27);
    int r = i - o * (CC * 27);
    int c = r / 27;
    int k = r - c * 27;
    g_dcwt[(k * CC + c) * CC + o] = w[i];
}

// ---------------- deformable conv: 3-way tap split, smem weights, f32x2 ----------------
// blockIdx.z = tap group g; taps [9g, 9g+9). Partial (no bias) written to
// buffer {g_a3, g_h1, g_attn}[g]; summed (+dc_b) inside the c1 pointwise.
__global__ void __launch_bounds__(256) k_deform() {
    __shared__ __align__(16) float wt_s[CC * CC];   // [c][o] for current tap
    int s = blockIdx.x * blockDim.x + threadIdx.x;
    int b = blockIdx.y;
    int g = blockIdx.z;
    int z = s >> 10, y = (s >> 5) & 31, x = s & 31;
    const float* a   = g_a2  + (size_t)b * CC * SS;
    const float* off = g_off + (size_t)b * OFFC * SS + s;

    ull acc2[CC / 2];
    #pragma unroll
    for (int q = 0; q < CC / 2; q++) acc2[q] = 0ull;

    #pragma unroll 1
    for (int kt = g * 9; kt < g * 9 + 9; kt++) {
        __syncthreads();
        {
            const float4* src = (const float4*)(g_dcwt + kt * CC * CC);
            float4* dst = (float4*)wt_s;
            for (int i = threadIdx.x; i < CC * CC / 4; i += blockDim.x)
                dst[i] = src[i];
        }
        __syncthreads();

        int kd = kt / 9 - 1, kh = (kt / 3) % 3 - 1, kw = kt % 3 - 1;
        float zf = (float)(z + kd) + off[(kt * 3 + 0) * SS];
        float yf = (float)(y + kh) + off[(kt * 3 + 1) * SS];
        float xf = (float)(x + kw) + off[(kt * 3 + 2) * SS];
        float z0 = floorf(zf), y0 = floorf(yf), x0 = floorf(xf);
        float tz = zf - z0, ty = yf - y0, tx = xf - x0;
        int iz0 = (int)z0, iy0 = (int)y0, ix0 = (int)x0;

        int idx8[8];
        ull w8v[8];
        #pragma unroll
        for (int dz = 0; dz < 2; dz++)
        #pragma unroll
        for (int dy = 0; dy < 2; dy++)
        #pragma unroll
        for (int dx = 0; dx < 2; dx++) {
            int j = dz * 4 + dy * 2 + dx;
            int zi = iz0 + dz, yi = iy0 + dy, xi = ix0 + dx;
            bool valid = (zi >= 0 && zi < 32 && yi >= 0 && yi < 32 && xi >= 0 && xi < 32);
            float wg = (dz ? tz : 1.f - tz) * (dy ? ty : 1.f - ty) * (dx ? tx : 1.f - tx);
            int zc = min(max(zi, 0), 31), yc = min(max(yi, 0), 31), xc = min(max(xi, 0), 31);
            idx8[j] = (zc << 10) + (yc << 5) + xc;
            float wf = valid ? wg : 0.f;
            w8v[j] = pack2(wf, wf);
        }

        for (int c = 0; c < CC; c += 2) {
            const float* ac0 = a + c * SS;
            const float* ac1 = ac0 + SS;
            ull valv = 0ull;
            #pragma unroll
            for (int j = 0; j < 8; j++)
                fma2(valv, pack2(ac0[idx8[j]], ac1[idx8[j]]), w8v[j]);
            float v0, v1;
            unpack2(v0, v1, valv);
            ull vv0 = pack2(v0, v0), vv1 = pack2(v1, v1);

            const ulonglong2* w0 = (const ulonglong2*)(wt_s + (c + 0) * CC);
            const ulonglong2* w1 = (const ulonglong2*)(wt_s + (c + 1) * CC);
            #pragma unroll
            for (int q = 0; q < CC / 4; q++) {
                ulonglong2 wa = w0[q];
                fma2(acc2[2 * q + 0], wa.x, vv0);
                fma2(acc2[2 * q + 1], wa.y, vv0);
            }
            #pragma unroll
            for (int q = 0; q < CC / 4; q++) {
                ulonglong2 wb = w1[q];
                fma2(acc2[2 * q + 0], wb.x, vv1);
                fma2(acc2[2 * q + 1], wb.y, vv1);
            }
        }
    }

    int outid = (g == 0) ? 5 : (g == 1) ? 7 : 8;
    float* ob = bufsel(outid, nullptr) + (size_t)b * CC * SS + s;
    #pragma unroll
    for (int q = 0; q < CC / 2; q++) {
        float a0, a1;
        unpack2(a0, a1, acc2[q]);
        ob[(2 * q + 0) * SS] = a0;
        ob[(2 * q + 1) * SS] = a1;
    }
}

// ---------------- launch: kernel launches ONLY ----------------
extern "C" void kernel_launch(void* const* d_in, const int* in_sizes, int n_in,
                              void* d_out, int out_size) {
    const float* x     = (const float*)d_in[0];
    const float* ln_s  = (const float*)d_in[1];
    const float* ln_b  = (const float*)d_in[2];
    const float* gamma = (const float*)d_in[3];
    const float* p1_w  = (const float*)d_in[4];
    const float* p1_b  = (const float*)d_in[5];
    const float* p2_w  = (const float*)d_in[6];
    const float* p2_b  = (const float*)d_in[7];
    const float* c0_w  = (const float*)d_in[8];
    const float* c0_b  = (const float*)d_in[9];
    const float* cs_w  = (const float*)d_in[10];
    const float* cs_b  = (const float*)d_in[11];
    const float* off_w = (const float*)d_in[12];
    const float* off_b = (const float*)d_in[13];
    const float* dc_w  = (const float*)d_in[14];
    const float* dc_b  = (const float*)d_in[15];
    const float* c1_w  = (const float*)d_in[16];
    const float* c1_b  = (const float*)d_in[17];
    const float* u1_w  = (const float*)d_in[18];
    const float* bn1_s = (const float*)d_in[19];
    const float* bn1_b = (const float*)d_in[20];
    const float* bn1_m = (const float*)d_in[21];
    const float* bn1_v = (const float*)d_in[22];
    const float* u2_w  = (const float*)d_in[23];
    const float* bn2_s = (const float*)d_in[24];
    const float* bn2_b = (const float*)d_in[25];
    const float* bn2_m = (const float*)d_in[26];
    const float* bn2_v = (const float*)d_in[27];
    const float* pr_w  = (const float*)d_in[28];
    const float* pr_b  = (const float*)d_in[29];
    float* out = (float*)d_out;

    dim3 pwGrid((BB * SS) / 256);
    dim3 dwGrid(SS / 1024, CC, BB);
    dim3 c3OffGrid(SS / 512, 3, BB);
    dim3 c3UGrid(SS / 512, 2, BB);

    // 1. fused LayerNorm + proj_1 + GELU: x -> g_xn (0), g_u (1)
    k_lnpw<<<pwGrid, 256>>>(x, ln_s, ln_b, p1_w, p1_b);
    // 2. depthwise 5x5x5 pad 2: g_u -> g_a1 (2)
    k_dw<5, 2, 1><<<dwGrid, 256>>>(1, c0_w, c0_b, 2);
    // 3. depthwise 7x7x7 dil 3 pad 9: g_a1 -> g_a2 (3)
    k_dw<7, 9, 3><<<dwGrid, 256>>>(2, cs_w, cs_b, 3);
    // 4. offset conv 3x3x3 -> 81 channels: g_a2 -> g_off (4)
    k_c3g<27, 28, 8><<<c3OffGrid, 256>>>(3, off_w, off_b,
                                         nullptr, nullptr, nullptr, nullptr,
                                         -1, 4, OFFC, 0);
    // 5. transpose deform weights
    k_wt<<<(CC * CC * 27 + 255) / 256, 256>>>(dc_w);
    // 6. deformable conv, 3 tap groups: partials -> g_a3 (5), g_h1 (7), g_attn (8)
    k_deform<<<dim3(SS / 256, BB, 3), 256>>>();
    // 7. c1 1x1x1 on (sum of partials + dc_b), gate mult with g_u -> g_a1 (2)
    k_pw48<<<pwGrid, 256>>>(5, nullptr, c1_w, c1_b, 1, nullptr, nullptr, dc_b,
                            2, nullptr, 1);
    // 8. proj_2 + shortcut + gamma residual: g_a1, aux x, g_xn -> g_skip (6)
    k_pw48<<<pwGrid, 256>>>(2, nullptr, p2_w, p2_b, -1, x, gamma, nullptr,
                            6, nullptr, 2);
    // 9. u1 conv3 + BN1 + leaky: g_skip -> g_h1 (7)
    k_c3g<24, 24, 8><<<c3UGrid, 256>>>(6, u1_w, nullptr,
                                       bn1_s, bn1_b, bn1_m, bn1_v,
                                       -1, 7, CC, 1);
    // 10. u2 conv3 + BN2 + skip + leaky: g_h1 -> g_attn (8)
    k_c3g<24, 24, 8><<<c3UGrid, 256>>>(7, u2_w, nullptr,
                                       bn2_s, bn2_b, bn2_m, bn2_v,
                                       6, 8, CC, 2);
    // 11. projconv 1x1x1 + skip -> out (external)
    k_pw48<<<pwGrid, 256>>>(8, nullptr, pr_w, pr_b, 6, nullptr, nullptr, nullptr,
                            -1, out, 3);
}

// round 9
// speedup vs baseline: 3.8692x; 1.0056x over previous
#include <cuda_runtime.h>
#include <math.h>

// Problem constants (B=2, C=48, 32^3 volume)
#define BB   2
#define CC   48
#define SS   (32*32*32)          // 32768
#define OFFC 81

typedef unsigned long long ull;

// ---------------- f32x2 packed helpers (sm_100+) ----------------
__device__ __forceinline__ ull pack2(float a, float b) {
    ull r;
    asm("mov.b64 %0, {%1, %2};" : "=l"(r) : "f"(a), "f"(b));
    return r;
}
__device__ __forceinline__ void fma2(ull& d, ull a, ull b) {
    asm("fma.rn.f32x2 %0, %1, %2, %0;" : "+l"(d) : "l"(a), "l"(b));
}
__device__ __forceinline__ void unpack2(float& lo, float& hi, ull v) {
    asm("mov.b64 {%0, %1}, %2;" : "=f"(lo), "=f"(hi) : "l"(v));
}

// ---------------- scratch (device globals; allocation-free) ----------------
__device__ float g_xn  [BB*CC*SS];   // 0
__device__ float g_u   [BB*CC*SS];   // 1
__device__ float g_a1  [BB*CC*SS];   // 2
__device__ float g_a2  [BB*CC*SS];   // 3
__device__ float g_off [BB*OFFC*SS]; // 4
__device__ float g_a3  [BB*CC*SS];   // 5  (deform partial 0)
__device__ float g_skip[BB*CC*SS];   // 6
__device__ float g_h1  [BB*CC*SS];   // 7  (deform partial 1, later u1 out)
__device__ float g_attn[BB*CC*SS];   // 8  (deform partial 2, later u2 out)
__device__ float g_dcwt[27*CC*CC];   // dc_w transposed to [tap][c][o]

__device__ __forceinline__ float* bufsel(int id, const float* ext) {
    switch (id) {
        case 0: return g_xn;   case 1: return g_u;    case 2: return g_a1;
        case 3: return g_a2;   case 4: return g_off;  case 5: return g_a3;
        case 6: return g_skip; case 7: return g_h1;   case 8: return g_attn;
    }
    return (float*)ext;
}

// ---------------- fused LayerNorm + proj_1 + GELU ----------------
__global__ void __launch_bounds__(256) k_lnpw(
    const float* __restrict__ x,
    const float* __restrict__ ls, const float* __restrict__ lb,
    const float* __restrict__ w,  const float* __restrict__ bias)
{
    __shared__ __align__(16) float ws2[CC * CC];   // [c][o], o contiguous
    __shared__ float bs[CC];
    for (int i = threadIdx.x; i < CC * CC; i += blockDim.x) {
        int o = i / CC, c = i - o * CC;
        ws2[c * CC + o] = w[i];
    }
    if (threadIdx.x < CC) bs[threadIdx.x] = bias[threadIdx.x];
    __syncthreads();

    int i = blockIdx.x * blockDim.x + threadIdx.x;
    int b = i >> 15, s = i & (SS - 1);
    const float* xb = x + (size_t)b * CC * SS + s;

    float s1 = 0.f, s2 = 0.f;
    #pragma unroll 8
    for (int c = 0; c < CC; c++) { float v = xb[c * SS]; s1 += v; s2 += v * v; }
    float mu  = s1 * (1.f / CC);
    float var = s2 * (1.f / CC) - mu * mu;
    float inv = rsqrtf(var + 1e-5f);

    float* xnp = g_xn + (size_t)b * CC * SS + s;

    ull acc2[CC / 2];
    #pragma unroll
    for (int q = 0; q < CC / 2; q++) acc2[q] = 0ull;

    const ulonglong2* wrow = (const ulonglong2*)ws2;
    #pragma unroll 4
    for (int c = 0; c < CC; c++) {
        float v = (xb[c * SS] - mu) * inv * ls[c] + lb[c];
        xnp[c * SS] = v;
        ull vv = pack2(v, v);
        #pragma unroll
        for (int q = 0; q < CC / 4; q++) {
            ulonglong2 wq = wrow[c * (CC / 4) + q];
            fma2(acc2[2 * q + 0], wq.x, vv);
            fma2(acc2[2 * q + 1], wq.y, vv);
        }
    }

    float* up = g_u + (size_t)b * CC * SS + s;
    #pragma unroll
    for (int q = 0; q < CC / 2; q++) {
        float a0, a1;
        unpack2(a0, a1, acc2[q]);
        float v0 = a0 + bs[2 * q + 0];
        float v1 = a1 + bs[2 * q + 1];
        up[(2 * q + 0) * SS] = 0.5f * v0 * (1.f + erff(v0 * 0.70710678118654752f));
        up[(2 * q + 1) * SS] = 0.5f * v1 * (1.f + erff(v1 * 0.70710678118654752f));
    }
}

// ---------------- 1x1x1 pointwise 48x48, f32x2 output pairs ----------------
// mode 1: out = aux1 * (acc + bias[o]); input = a3+h1+attn partials + dcb[c]
// mode 2: out = aux1 + gamma[o]*(acc + bias[o] + g_xn)
// mode 3: out = aux1 + acc + bias[o]
__global__ void __launch_bounds__(256) k_pw48(
    int in_id, const float* __restrict__ ext_in,
    const float* __restrict__ w, const float* __restrict__ bias,
    int a1_id, const float* __restrict__ ext_a1,
    const float* __restrict__ gamma,
    const float* __restrict__ dcb,
    int out_id, float* __restrict__ ext_out,
    int mode)
{
    __shared__ __align__(16) float ws2[CC * CC];   // [c][o], o contiguous
    __shared__ float bs[CC];
    __shared__ float dcs[CC];
    for (int i = threadIdx.x; i < CC * CC; i += blockDim.x) {
        int o = i / CC, c = i - o * CC;
        ws2[c * CC + o] = w[i];
    }
    if (threadIdx.x < CC) {
        bs[threadIdx.x] = bias[threadIdx.x];
        dcs[threadIdx.x] = (dcb != nullptr) ? dcb[threadIdx.x] : 0.f;
    }
    __syncthreads();

    int i = blockIdx.x * blockDim.x + threadIdx.x;
    int b = i >> 15, s = i & (SS - 1);
    size_t base = (size_t)b * CC * SS + s;
    const float* in = bufsel(in_id, ext_in) + base;
    const float* pp1 = g_h1 + base;    // deform partial 1 (mode 1 only)
    const float* pp2 = g_attn + base;  // deform partial 2 (mode 1 only)

    ull acc2[CC / 2];
    #pragma unroll
    for (int q = 0; q < CC / 2; q++) acc2[q] = 0ull;

    const ulonglong2* wrow = (const ulonglong2*)ws2;
    if (mode == 1) {
        #pragma unroll 4
        for (int c = 0; c < CC; c++) {
            float v = in[c * SS] + pp1[c * SS] + pp2[c * SS] + dcs[c];
            ull vv = pack2(v, v);
            #pragma unroll
            for (int q = 0; q < CC / 4; q++) {
                ulonglong2 wq = wrow[c * (CC / 4) + q];
                fma2(acc2[2 * q + 0], wq.x, vv);
                fma2(acc2[2 * q + 1], wq.y, vv);
            }
        }
    } else {
        #pragma unroll 4
        for (int c = 0; c < CC; c++) {
            float v = in[c * SS];
            ull vv = pack2(v, v);
            #pragma unroll
            for (int q = 0; q < CC / 4; q++) {
                ulonglong2 wq = wrow[c * (CC / 4) + q];
                fma2(acc2[2 * q + 0], wq.x, vv);
                fma2(acc2[2 * q + 1], wq.y, vv);
            }
        }
    }

    float acc[CC];
    #pragma unroll
    for (int q = 0; q < CC / 2; q++) unpack2(acc[2 * q], acc[2 * q + 1], acc2[q]);

    float* outp = bufsel(out_id, (const float*)ext_out) + base;
    const float* a1p = bufsel(a1_id, ext_a1) + base;
    const float* a2p = g_xn + base;

    if (mode == 1) {
        #pragma unroll
        for (int o = 0; o < CC; o++)
            outp[o * SS] = a1p[o * SS] * (acc[o] + bs[o]);
    } else if (mode == 2) {
        #pragma unroll
        for (int o = 0; o < CC; o++)
            outp[o * SS] = a1p[o * SS] + gamma[o] * (acc[o] + bs[o] + a2p[o * SS]);
    } else {
        #pragma unroll
        for (int o = 0; o < CC; o++)
            outp[o * SS] = a1p[o * SS] + acc[o] + bs[o];
    }
}

// ---------------- depthwise KxKxK: 4 x-adjacent outputs/thread, float4 rows ----------------
template<int K, int PAD, int DIL>
__global__ void __launch_bounds__(256) k_dw(int in_id, const float* __restrict__ w,
                                            const float* __restrict__ bias, int out_id) {
    constexpr int LOW = -(((PAD) + 3) / 4) * 4;
    constexpr int HI  = 3 + (K - 1) * DIL - PAD;
    constexpr int NCH = (HI - LOW) / 4 + 1;
    __shared__ float ws[K * K * K];
    int c = blockIdx.y, b = blockIdx.z;
    for (int i = threadIdx.x; i < K * K * K; i += blockDim.x)
        ws[i] = w[c * K * K * K + i];
    __syncthreads();
    int s = blockIdx.x * 1024 + threadIdx.x * 4;
    int z = s >> 10, y = (s >> 5) & 31, x0 = s & 31;
    const float* ib = bufsel(in_id, nullptr) + ((size_t)b * CC + c) * SS;

    float b0 = bias[c];
    float acc[4] = {b0, b0, b0, b0};

    #pragma unroll
    for (int i = 0; i < K; i++) {
        int zz = z + i * DIL - PAD;
        if ((unsigned)zz >= 32u) continue;
        #pragma unroll
        for (int j = 0; j < K; j++) {
            int yy = y + j * DIL - PAD;
            if ((unsigned)yy >= 32u) continue;
            const float* row = ib + (zz << 10) + (yy << 5);
            float v[NCH * 4];
            #pragma unroll
            for (int ch = 0; ch < NCH; ch++) {
                int xb = x0 + LOW + ch * 4;
                if (xb >= 0 && xb <= 28) {
                    float4 t = *(const float4*)(row + xb);
                    v[ch * 4 + 0] = t.x; v[ch * 4 + 1] = t.y;
                    v[ch * 4 + 2] = t.z; v[ch * 4 + 3] = t.w;
                } else {
                    v[ch * 4 + 0] = 0.f; v[ch * 4 + 1] = 0.f;
                    v[ch * 4 + 2] = 0.f; v[ch * 4 + 3] = 0.f;
                }
            }
            const float* wr = ws + (i * K + j) * K;
            #pragma unroll
            for (int l = 0; l < K; l++) {
                float wv = wr[l];
                #pragma unroll
                for (int u = 0; u < 4; u++)
                    acc[u] += wv * v[u + l * DIL - PAD - LOW];
            }
        }
    }
    float* op = bufsel(out_id, nullptr) + ((size_t)b * CC + c) * SS + s;
    *(float4*)op = make_float4(acc[0], acc[1], acc[2], acc[3]);
}

// ---------------- dense 3x3x3 conv, 2 voxels/thread, row-streamed, f32x2 ----------------
// Row-streamed: per (c,kd,kh) load 4 x-values, immediately fan out the 3 kw taps,
// so only 4 neighborhood values are ever live (was 36) -> ~2 blocks/SM occupancy.
// mode 0: +bias; 1: leaky(bn); 2: leaky(bn + skip)
template<int NO, int NO4, int CCH>
__global__ void __launch_bounds__(256, 2) k_c3g(
    int in_id, const float* __restrict__ w,
    const float* __restrict__ bias,
    const float* __restrict__ bs2, const float* __restrict__ bbp,
    const float* __restrict__ bm, const float* __restrict__ bv,
    int skip_id, int out_id, int O, int mode)
{
    __shared__ __align__(16) float ws[CCH * 27 * NO4];
    const int o0 = blockIdx.y * NO;
    const int b  = blockIdx.z;
    const int s  = blockIdx.x * 512 + threadIdx.x * 2;
    const int z = s >> 10, y = (s >> 5) & 31, x0 = s & 31;
    const float* ib = bufsel(in_id, nullptr) + (size_t)b * CC * SS;

    ull accA[NO4 / 2], accB[NO4 / 2];
    #pragma unroll
    for (int q = 0; q < NO4 / 2; q++) { accA[q] = 0ull; accB[q] = 0ull; }

    for (int cbase = 0; cbase < CC; cbase += CCH) {
        __syncthreads();
        for (int gidx = threadIdx.x; gidx < NO * CCH * 27; gidx += blockDim.x) {
            int oL  = gidx / (CCH * 27);
            int r   = gidx - oL * (CCH * 27);
            int cL  = r / 27;
            int tap = r - cL * 27;
            ws[(cL * 27 + tap) * NO4 + oL] =
                w[(size_t)(o0 + oL) * (CC * 27) + (cbase + cL) * 27 + tap];
        }
        __syncthreads();

        for (int cL = 0; cL < CCH; cL++) {
            const float* ic = ib + (cbase + cL) * SS;
            const ulonglong2* wbase = (const ulonglong2*)(ws + cL * 27 * NO4);
            #pragma unroll
            for (int kd = 0; kd < 3; kd++) {
                int zz = z + kd - 1; bool vz = (unsigned)zz < 32u;
                #pragma unroll
                for (int kh = 0; kh < 3; kh++) {
                    int yy = y + kh - 1; bool vy = (unsigned)yy < 32u;
                    int rbase = (zz << 10) + (yy << 5);
                    bool vzy = vz && vy;
                    // 4 x-values for this row: x0-1 .. x0+2
                    float r0 = (vzy && x0 >= 1)  ? ic[rbase + x0 - 1] : 0.f;
                    float r1 =  vzy              ? ic[rbase + x0    ] : 0.f;
                    float r2 =  vzy              ? ic[rbase + x0 + 1] : 0.f;
                    float r3 = (vzy && x0 <= 29) ? ic[rbase + x0 + 2] : 0.f;
                    int taprow = (kd * 3 + kh) * 3;
                    #pragma unroll
                    for (int kw = 0; kw < 3; kw++) {
                        float vA = (kw == 0) ? r0 : (kw == 1) ? r1 : r2;
                        float vB = (kw == 0) ? r1 : (kw == 1) ? r2 : r3;
                        ull vvA = pack2(vA, vA);
                        ull vvB = pack2(vB, vB);
                        const ulonglong2* wrow = wbase + (taprow + kw) * (NO4 / 4);
                        #pragma unroll
                        for (int q = 0; q < NO4 / 4; q++) {
                            ulonglong2 wq = wrow[q];
                            fma2(accA[2 * q + 0], wq.x, vvA);
                            fma2(accA[2 * q + 1], wq.y, vvA);
                            fma2(accB[2 * q + 0], wq.x, vvB);
                            fma2(accB[2 * q + 1], wq.y, vvB);
                        }
                    }
                }
            }
        }
    }

    float aA[NO4], aB[NO4];
    #pragma unroll
    for (int q = 0; q < NO4 / 2; q++) {
        unpack2(aA[2 * q], aA[2 * q + 1], accA[q]);
        unpack2(aB[2 * q], aB[2 * q + 1], accB[q]);
    }

    float* outb = bufsel(out_id, nullptr) + (size_t)b * O * SS + s;
    if (mode == 0) {
        #pragma unroll
        for (int o = 0; o < NO; o++) {
            float bb = bias[o0 + o];
            *(float2*)&outb[(o0 + o) * SS] = make_float2(aA[o] + bb, aB[o] + bb);
        }
    } else {
        const float* skp = (mode == 2) ? bufsel(skip_id, nullptr) + (size_t)b * O * SS + s
                                       : nullptr;
        #pragma unroll
        for (int o = 0; o < NO; o++) {
            int og = o0 + o;
            float scale = bs2[og] * rsqrtf(bv[og] + 1e-5f);
            float sh = bbp[og] - bm[og] * scale;
            float hA = aA[o] * scale + sh;
            float hB = aB[o] * scale + sh;
            if (mode == 2) { hA += skp[og * SS]; hB += skp[og * SS + 1]; }
            hA = (hA >= 0.f) ? hA : 0.01f * hA;
            hB = (hB >= 0.f) ? hB : 0.01f * hB;
            *(float2*)&outb[og * SS] = make_float2(hA, hB);
        }
    }
}

// ---------------- transpose dc_w [o][c][k] -> [k][c][o] ----------------
__global__ void k_wt(const float* __restrict__ w) {
    int i = blockIdx.x * blockDim.x + threadIdx.x;
    if (i >= CC * CC * 27) return;
    int o = i / (CC * 27);
    int r = i - o * (CC * 27);
    int c = r / 27;
    int k = r - c * 27;
    g_dcwt[(k * CC + c) * CC + o] = w[i];
}

// ---------------- deformable conv: 3-way tap split, smem weights, f32x2 ----------------
__global__ void __launch_bounds__(256, 2) k_deform() {
    __shared__ __align__(16) float wt_s[CC * CC];   // [c][o] for current tap
    int s = blockIdx.x * blockDim.x + threadIdx.x;
    int b = blockIdx.y;
    int g = blockIdx.z;
    int z = s >> 10, y = (s >> 5) & 31, x = s & 31;
    const float* a   = g_a2  + (size_t)b * CC * SS;
    const float* off = g_off + (size_t)b * OFFC * SS + s;

    ull acc2[CC / 2];
    #pragma unroll
    for (int q = 0; q < CC / 2; q++) acc2[q] = 0ull;

    #pragma unroll 1
    for (int kt = g * 9; kt < g * 9 + 9; kt++) {
        __syncthreads();
        {
            const float4* src = (const float4*)(g_dcwt + kt * CC * CC);
            float4* dst = (float4*)wt_s;
            for (int i = threadIdx.x; i < CC * CC / 4; i += blockDim.x)
                dst[i] = src[i];
        }
        __syncthreads();

        int kd = kt / 9 - 1, kh = (kt / 3) % 3 - 1, kw = kt % 3 - 1;
        float zf = (float)(z + kd) + off[(kt * 3 + 0) * SS];
        float yf = (float)(y + kh) + off[(kt * 3 + 1) * SS];
        float xf = (float)(x + kw) + off[(kt * 3 + 2) * SS];
        float z0 = floorf(zf), y0 = floorf(yf), x0 = floorf(xf);
        float tz = zf - z0, ty = yf - y0, tx = xf - x0;
        int iz0 = (int)z0, iy0 = (int)y0, ix0 = (int)x0;

        int idx8[8];
        ull w8v[8];
        #pragma unroll
        for (int dz = 0; dz < 2; dz++)
        #pragma unroll
        for (int dy = 0; dy < 2; dy++)
        #pragma unroll
        for (int dx = 0; dx < 2; dx++) {
            int j = dz * 4 + dy * 2 + dx;
            int zi = iz0 + dz, yi = iy0 + dy, xi = ix0 + dx;
            bool valid = (zi >= 0 && zi < 32 && yi >= 0 && yi < 32 && xi >= 0 && xi < 32);
            float wg = (dz ? tz : 1.f - tz) * (dy ? ty : 1.f - ty) * (dx ? tx : 1.f - tx);
            int zc = min(max(zi, 0), 31), yc = min(max(yi, 0), 31), xc = min(max(xi, 0), 31);
            idx8[j] = (zc << 10) + (yc << 5) + xc;
            float wf = valid ? wg : 0.f;
            w8v[j] = pack2(wf, wf);
        }

        for (int c = 0; c < CC; c += 2) {
            const float* ac0 = a + c * SS;
            const float* ac1 = ac0 + SS;
            ull valv = 0ull;
            #pragma unroll
            for (int j = 0; j < 8; j++)
                fma2(valv, pack2(ac0[idx8[j]], ac1[idx8[j]]), w8v[j]);
            float v0, v1;
            unpack2(v0, v1, valv);
            ull vv0 = pack2(v0, v0), vv1 = pack2(v1, v1);

            const ulonglong2* w0 = (const ulonglong2*)(wt_s + (c + 0) * CC);
            const ulonglong2* w1 = (const ulonglong2*)(wt_s + (c + 1) * CC);
            #pragma unroll
            for (int q = 0; q < CC / 4; q++) {
                ulonglong2 wa = w0[q];
                fma2(acc2[2 * q + 0], wa.x, vv0);
                fma2(acc2[2 * q + 1], wa.y, vv0);
            }
            #pragma unroll
            for (int q = 0; q < CC / 4; q++) {
                ulonglong2 wb = w1[q];
                fma2(acc2[2 * q + 0], wb.x, vv1);
                fma2(acc2[2 * q + 1], wb.y, vv1);
            }
        }
    }

    int outid = (g == 0) ? 5 : (g == 1) ? 7 : 8;
    float* ob = bufsel(outid, nullptr) + (size_t)b * CC * SS + s;
    #pragma unroll
    for (int q = 0; q < CC / 2; q++) {
        float a0, a1;
        unpack2(a0, a1, acc2[q]);
        ob[(2 * q + 0) * SS] = a0;
        ob[(2 * q + 1) * SS] = a1;
    }
}

// ---------------- launch: kernel launches ONLY ----------------
extern "C" void kernel_launch(void* const* d_in, const int* in_sizes, int n_in,
                              void* d_out, int out_size) {
    const float* x     = (const float*)d_in[0];
    const float* ln_s  = (const float*)d_in[1];
    const float* ln_b  = (const float*)d_in[2];
    const float* gamma = (const float*)d_in[3];
    const float* p1_w  = (const float*)d_in[4];
    const float* p1_b  = (const float*)d_in[5];
    const float* p2_w  = (const float*)d_in[6];
    const float* p2_b  = (const float*)d_in[7];
    const float* c0_w  = (const float*)d_in[8];
    const float* c0_b  = (const float*)d_in[9];
    const float* cs_w  = (const float*)d_in[10];
    const float* cs_b  = (const float*)d_in[11];
    const float* off_w = (const float*)d_in[12];
    const float* off_b = (const float*)d_in[13];
    const float* dc_w  = (const float*)d_in[14];
    const float* dc_b  = (const float*)d_in[15];
    const float* c1_w  = (const float*)d_in[16];
    const float* c1_b  = (const float*)d_in[17];
    const float* u1_w  = (const float*)d_in[18];
    const float* bn1_s = (const float*)d_in[19];
    const float* bn1_b = (const float*)d_in[20];
    const float* bn1_m = (const float*)d_in[21];
    const float* bn1_v = (const float*)d_in[22];
    const float* u2_w  = (const float*)d_in[23];
    const float* bn2_s = (const float*)d_in[24];
    const float* bn2_b = (const float*)d_in[25];
    const float* bn2_m = (const float*)d_in[26];
    const float* bn2_v = (const float*)d_in[27];
    const float* pr_w  = (const float*)d_in[28];
    const float* pr_b  = (const float*)d_in[29];
    float* out = (float*)d_out;

    dim3 pwGrid((BB * SS) / 256);
    dim3 dwGrid(SS / 1024, CC, BB);
    dim3 c3OffGrid(SS / 512, 3, BB);
    dim3 c3UGrid(SS / 512, 2, BB);

    // 1. fused LayerNorm + proj_1 + GELU: x -> g_xn (0), g_u (1)
    k_lnpw<<<pwGrid, 256>>>(x, ln_s, ln_b, p1_w, p1_b);
    // 2. depthwise 5x5x5 pad 2: g_u -> g_a1 (2)
    k_dw<5, 2, 1><<<dwGrid, 256>>>(1, c0_w, c0_b, 2);
    // 3. depthwise 7x7x7 dil 3 pad 9: g_a1 -> g_a2 (3)
    k_dw<7, 9, 3><<<dwGrid, 256>>>(2, cs_w, cs_b, 3);
    // 4. offset conv 3x3x3 -> 81 channels: g_a2 -> g_off (4)
    k_c3g<27, 28, 8><<<c3OffGrid, 256>>>(3, off_w, off_b,
                                         nullptr, nullptr, nullptr, nullptr,
                                         -1, 4, OFFC, 0);
    // 5. transpose deform weights
    k_wt<<<(CC * CC * 27 + 255) / 256, 256>>>(dc_w);
    // 6. deformable conv, 3 tap groups: partials -> g_a3 (5), g_h1 (7), g_attn (8)
    k_deform<<<dim3(SS / 256, BB, 3), 256>>>();
    // 7. c1 1x1x1 on (sum of partials + dc_b), gate mult with g_u -> g_a1 (2)
    k_pw48<<<pwGrid, 256>>>(5, nullptr, c1_w, c1_b, 1, nullptr, nullptr, dc_b,
                            2, nullptr, 1);
    // 8. proj_2 + shortcut + gamma residual: g_a1, aux x, g_xn -> g_skip (6)
    k_pw48<<<pwGrid, 256>>>(2, nullptr, p2_w, p2_b, -1, x, gamma, nullptr,
                            6, nullptr, 2);
    // 9. u1 conv3 + BN1 + leaky: g_skip -> g_h1 (7)
    k_c3g<24, 24, 8><<<c3UGrid, 256>>>(6, u1_w, nullptr,
                                       bn1_s, bn1_b, bn1_m, bn1_v,
                                       -1, 7, CC, 1);
    // 10. u2 conv3 + BN2 + skip + leaky: g_h1 -> g_attn (8)
    k_c3g<24, 24, 8><<<c3UGrid, 256>>>(7, u2_w, nullptr,
                                       bn2_s, bn2_b, bn2_m, bn2_v,
                                       6, 8, CC, 2);
    // 11. projconv 1x1x1 + skip -> out (external)
    k_pw48<<<pwGrid, 256>>>(8, nullptr, pr_w, pr_b, 6, nullptr, nullptr, nullptr,
                            -1, out, 3);
}